// round 2
// baseline (speedup 1.0000x reference)
#include <cuda_runtime.h>
#include <math.h>

#define H    2048
#define DIN  784
#define DOUT 10

// ---------------- scratch (device globals; no allocations allowed) ----------------
__device__ float g_u0[DIN], g_l0[DIN];
__device__ float g_ubL[3 * H], g_lbL[3 * H];          // pre-SPU bounds per hidden layer
__device__ float g_sus[3 * H], g_sui[3 * H];          // SPU upper slope / intercept
__device__ float g_sls[3 * H], g_sli[3 * H];          // SPU lower slope / intercept
__device__ float g_pub[3 * H], g_plb[3 * H];          // post-SPU refined bounds
__device__ float g_ub4[DOUT], g_lb4[DOUT];
__device__ float g_W0[(long)H * H];
__device__ float g_W1[(long)H * H];
__device__ float g_B0[H], g_B1[H];

// ---------------- device helpers ----------------
__device__ __forceinline__ float sigm_(float x) { return 1.0f / (1.0f + expf(-x)); }
__device__ __forceinline__ float spu_(float x) {
    return (x >= 0.0f) ? (x * x - 0.5f) : (sigm_(-x) - 1.0f);
}

__device__ __forceinline__ float block_reduce(float v) {
    __shared__ float sh[32];
    int tid = threadIdx.x;
#pragma unroll
    for (int o = 16; o > 0; o >>= 1) v += __shfl_down_sync(0xffffffffu, v, o);
    if ((tid & 31) == 0) sh[tid >> 5] = v;
    __syncthreads();
    float r = 0.0f;
    if (tid < 32) {
        int nw = ((int)blockDim.x + 31) >> 5;
        r = (tid < nw) ? sh[tid] : 0.0f;
#pragma unroll
        for (int o = 16; o > 0; o >>= 1) r += __shfl_down_sync(0xffffffffu, r, o);
    }
    __syncthreads();
    return r; // valid in tid 0
}

// ---------------- kernels ----------------
__global__ void k_init_bounds(const float* __restrict__ in, const float* __restrict__ epsp,
                              float* __restrict__ u0, float* __restrict__ l0) {
    int i = blockIdx.x * blockDim.x + threadIdx.x;
    if (i >= DIN) return;
    float e = epsp[0];
    float u = fminf(in[i] + e, 1.0f);
    float l = fmaxf(in[i] - e, 0.0f);
    u0[i] = (u - 0.1307f) / 0.3081f;
    l0[i] = (l - 0.1307f) / 0.3081f;
}

// interval bounds of W x + b given elementwise box [lb, ub]
__global__ void k_affine_interval(const float* __restrict__ W, const float* __restrict__ b,
                                  const float* __restrict__ ub, const float* __restrict__ lb,
                                  float* __restrict__ uo, float* __restrict__ lo, int cols) {
    int row = blockIdx.x;
    const float* wr = W + (long)row * cols;
    float su = 0.0f, sl = 0.0f;
    for (int j = threadIdx.x; j < cols; j += blockDim.x) {
        float w = wr[j];
        float p = fmaxf(w, 0.0f), n = fminf(w, 0.0f);
        float u = ub[j], l = lb[j];
        su += p * u + n * l;
        sl += p * l + n * u;
    }
    float rs = block_reduce(su);
    float rl = block_reduce(sl);
    if (threadIdx.x == 0) { uo[row] = rs + b[row]; lo[row] = rl + b[row]; }
}

// elementwise SPU relaxation analysis (exact reference math)
__global__ void k_spu(const float* __restrict__ ub, const float* __restrict__ lb,
                      float* __restrict__ us, float* __restrict__ ui,
                      float* __restrict__ ls, float* __restrict__ li,
                      float* __restrict__ pub, float* __restrict__ plb) {
    int i = blockIdx.x * blockDim.x + threadIdx.x;
    if (i >= H) return;
    float ux = ub[i], lx = lb[i];
    float uy = spu_(ux), ly = spu_(lx);
    float sj = (uy - ly) / (ux - lx);
    float ij = uy - sj * ux;
    bool right = lx > 0.0f;
    bool left  = ux <= 0.0f;
    float mid = 0.5f * (ux + lx);
    float sp = 2.0f * mid, ip = -mid * mid - 0.5f;
    float sm = sigm_(mid);
    float ssm = -sm * (1.0f - sm), ism = -sm - ssm * mid;
    float nub = fmaxf(uy, ly);
    float nlb, usv, uiv, lsv, liv;
    if (right) {
        usv = sj; uiv = ij; lsv = sp; liv = ip; nlb = fminf(uy, ly);
    } else if (left) {
        usv = ssm; uiv = ism; lsv = sj; liv = ij; nlb = fminf(uy, ly);
    } else {
        nlb = -0.5f;
        // lower constraint (crossing)
        float spu2 = 2.0f * ux, ipu = -ux * ux - 0.5f;
        float limit = spu2 * lx + ipu;
        float clm = (fabsf(lx) > ux) ? 1.0f : 0.0f;
        float clp = sigm_((clm - 0.5f) * 10.0f) * (ly - limit) + limit;
        if (clp < -0.5f) {
            float D = 4.0f * lx * lx - 4.0f * clp - 2.0f;
            float x2 = (2.0f * lx + sqrtf(fmaxf(D, 0.0f))) * 0.5f;
            lsv = 2.0f * x2; liv = -x2 * x2 - 0.5f;
        } else {
            lsv = (-0.5f - clp) / (0.0f - lx); liv = -0.5f;
        }
        // upper constraint (crossing)
        float sl_ = sigm_(lx);
        float ssl = -sl_ * (1.0f - sl_), isl = -sl_ - ssl * lx;
        float stv = ssl * ux + isl - uy;
        if (stv > 0.0f) {
            float L = lx, R = 0.0f;
#pragma unroll
            for (int t = 0; t < 10; t++) {
                float m = 0.5f * (L + R);
                float s = sigm_(m);
                float sms = -s * (1.0f - s), ims = -s - sms * m;
                bool mask = (sms * ux + ims - uy) > 0.0f;
                L = mask ? m : L;
                R = mask ? R : m;
            }
            float scp = sigm_(-5.0f) * (L - lx) + lx;
            float sc = sigm_(scp);
            usv = -sc * (1.0f - sc);
            uiv = -sc - usv * scp;
        } else {
            usv = sj; uiv = ij;
        }
    }
    us[i] = usv; ui[i] = uiv; ls[i] = lsv; li[i] = liv;
    pub[i] = nub; plb[i] = nlb;
}

// start a chain from a diagonal SPU constraint: row-scale the layer weights
__global__ void k_rowscale(const float* __restrict__ Wsrc, const float* __restrict__ bsrc,
                           const float* __restrict__ slope, const float* __restrict__ inter,
                           float* __restrict__ Wdst, float* __restrict__ Bdst, int cols) {
    int row = blockIdx.x;
    float s = slope[row];
    const float* ws = Wsrc + (long)row * cols;
    float* wd = Wdst + (long)row * cols;
    for (int j = threadIdx.x; j < cols; j += blockDim.x) wd[j] = s * ws[j];
    if (threadIdx.x == 0) Bdst[row] = s * bsrc[row] + inter[row];
}

// pass through a diagonal SPU layer: sign-split column scale, plus fused
// intercept reduction and fused bias matvec of the NEXT affine layer.
__global__ void k_colscale(const float* __restrict__ Wsrc, const float* __restrict__ Bsrc,
                           const float* __restrict__ sus, const float* __restrict__ sui,
                           const float* __restrict__ sls, const float* __restrict__ sli,
                           const float* __restrict__ blayer,
                           float* __restrict__ Wdst, float* __restrict__ Bdst, int upper) {
    int row = blockIdx.x;
    const float* ws = Wsrc + (long)row * H;
    float* wd = Wdst + (long)row * H;
    const float* ps = upper ? sus : sls;
    const float* pi = upper ? sui : sli;
    const float* ns = upper ? sls : sus;
    const float* ni = upper ? sli : sui;
    float acc = 0.0f;
    for (int j = threadIdx.x; j < H; j += blockDim.x) {
        float w = ws[j];
        float p = fmaxf(w, 0.0f), n = fminf(w, 0.0f);
        float nw = p * ps[j] + n * ns[j];
        wd[j] = nw;
        acc += p * pi[j] + n * ni[j] + nw * blayer[j];
    }
    float r = block_reduce(acc);
    if (threadIdx.x == 0) Bdst[row] = Bsrc[row] + r;
}

// final interval evaluation at input layer + bound refinement (min for upper, max for lower)
__global__ void k_interval(const float* __restrict__ W, const float* __restrict__ bvec,
                           const float* __restrict__ u0, const float* __restrict__ l0,
                           float* __restrict__ bio, int cols, int upper) {
    int row = blockIdx.x;
    const float* wr = W + (long)row * cols;
    const float* a = upper ? u0 : l0;
    const float* c = upper ? l0 : u0;
    float acc = 0.0f;
    for (int j = threadIdx.x; j < cols; j += blockDim.x) {
        float w = wr[j];
        acc += fmaxf(w, 0.0f) * a[j] + fminf(w, 0.0f) * c[j];
    }
    float r = block_reduce(acc);
    if (threadIdx.x == 0) {
        float v = r + bvec[row];
        bio[row] = upper ? fminf(bio[row], v) : fmaxf(bio[row], v);
    }
}

// plain SGEMM: C[MxN] = A[MxK] @ B[KxN], row-major, K % 8 == 0
#define BM 128
#define BN 128
#define BK 8
__global__ __launch_bounds__(256) void sgemm(const float* __restrict__ A,
                                             const float* __restrict__ B,
                                             float* __restrict__ C,
                                             int M, int N, int K) {
    __shared__ float As[BK][BM + 4];
    __shared__ float Bs[BK][BN];
    int tid = threadIdx.x;
    int tx = tid & 15, ty = tid >> 4;
    int rowBase = blockIdx.y * BM;
    int colBase = blockIdx.x * BN;
    float acc[8][8];
#pragma unroll
    for (int i = 0; i < 8; i++)
#pragma unroll
        for (int j = 0; j < 8; j++) acc[i][j] = 0.0f;

    for (int k0 = 0; k0 < K; k0 += BK) {
#pragma unroll
        for (int i = 0; i < 4; i++) {
            int idx = tid + i * 256;
            int r = idx >> 3, c = idx & 7;
            int gr = rowBase + r;
            As[c][r] = (gr < M) ? A[(long)gr * K + k0 + c] : 0.0f;
        }
#pragma unroll
        for (int i = 0; i < 4; i++) {
            int idx = tid + i * 256;
            int r = idx >> 7, c = idx & 127;
            int gc = colBase + c;
            Bs[r][c] = (gc < N) ? B[(long)(k0 + r) * N + gc] : 0.0f;
        }
        __syncthreads();
#pragma unroll
        for (int kk = 0; kk < BK; kk++) {
            float a[8], b[8];
#pragma unroll
            for (int m = 0; m < 8; m++) a[m] = As[kk][ty * 8 + m];
#pragma unroll
            for (int n = 0; n < 8; n++) b[n] = Bs[kk][tx * 8 + n];
#pragma unroll
            for (int m = 0; m < 8; m++)
#pragma unroll
                for (int n = 0; n < 8; n++) acc[m][n] += a[m] * b[n];
        }
        __syncthreads();
    }
#pragma unroll
    for (int m = 0; m < 8; m++) {
        int gr = rowBase + ty * 8 + m;
        if (gr >= M) continue;
#pragma unroll
        for (int n = 0; n < 8; n++) {
            int gc = colBase + tx * 8 + n;
            if (gc < N) C[(long)gr * N + gc] = acc[m][n];
        }
    }
}

__global__ void k_final_min(const float* __restrict__ lb4, float* __restrict__ out) {
    if (threadIdx.x == 0) {
        float m = lb4[0];
#pragma unroll
        for (int i = 1; i < DOUT; i++) m = fminf(m, lb4[i]);
        out[0] = m;
    }
}

// ---------------- host orchestration ----------------
struct P {
    const float *w1, *b1, *w2, *b2, *w3, *b3, *w4, *b4;
    float *U0, *L0, *UBL, *LBL, *SUS, *SUI, *SLS, *SLI, *PUB, *PLB, *UB4, *LB4;
    float *W0, *W1, *B0, *B1;
};

// Back-substitute a constraint matrix (M rows, coefficients over post-SPU vars of
// hidden layer `lvl`; lvl==0 means coefficients are already over the input) down
// to the input box and refine bound_io in place.
static void descend(const P& p, const float* sW, const float* sB, int M, int lvl,
                    int upper, float* bio) {
    const float* curW = sW;
    const float* curB = sB;
    float* bw[2] = {p.W0, p.W1};
    float* bb[2] = {p.B0, p.B1};
    const float* LW[3] = {p.w1, p.w2, p.w3};
    const float* LBv[3] = {p.b1, p.b2, p.b3};
    int pp = 0;
    for (int l = lvl; l >= 1; --l) {
        float* tW = bw[pp];
        float* tB = bb[pp];
        k_colscale<<<M, 256>>>(curW, curB,
                               p.SUS + (l - 1) * H, p.SUI + (l - 1) * H,
                               p.SLS + (l - 1) * H, p.SLI + (l - 1) * H,
                               LBv[l - 1], tW, tB, upper);
        int N = (l == 1) ? DIN : H;
        float* oW = bw[pp ^ 1];
        dim3 g((N + BN - 1) / BN, (M + BM - 1) / BM);
        sgemm<<<g, 256>>>(tW, LW[l - 1], oW, M, N, H);
        curW = oW;
        curB = tB;
        pp ^= 1;
    }
    k_interval<<<M, 256>>>(curW, curB, p.U0, p.L0, bio, DIN, upper);
}

extern "C" void kernel_launch(void* const* d_in, const int* in_sizes, int n_in,
                              void* d_out, int out_size) {
    (void)in_sizes; (void)n_in; (void)out_size;
    P p;
    const float* inputs = (const float*)d_in[0];
    const float* eps    = (const float*)d_in[1];
    p.w1 = (const float*)d_in[2]; p.b1 = (const float*)d_in[3];
    p.w2 = (const float*)d_in[4]; p.b2 = (const float*)d_in[5];
    p.w3 = (const float*)d_in[6]; p.b3 = (const float*)d_in[7];
    p.w4 = (const float*)d_in[8]; p.b4 = (const float*)d_in[9];
    float* out = (float*)d_out;

    cudaGetSymbolAddress((void**)&p.U0, g_u0);
    cudaGetSymbolAddress((void**)&p.L0, g_l0);
    cudaGetSymbolAddress((void**)&p.UBL, g_ubL);
    cudaGetSymbolAddress((void**)&p.LBL, g_lbL);
    cudaGetSymbolAddress((void**)&p.SUS, g_sus);
    cudaGetSymbolAddress((void**)&p.SUI, g_sui);
    cudaGetSymbolAddress((void**)&p.SLS, g_sls);
    cudaGetSymbolAddress((void**)&p.SLI, g_sli);
    cudaGetSymbolAddress((void**)&p.PUB, g_pub);
    cudaGetSymbolAddress((void**)&p.PLB, g_plb);
    cudaGetSymbolAddress((void**)&p.UB4, g_ub4);
    cudaGetSymbolAddress((void**)&p.LB4, g_lb4);
    cudaGetSymbolAddress((void**)&p.W0, g_W0);
    cudaGetSymbolAddress((void**)&p.W1, g_W1);
    cudaGetSymbolAddress((void**)&p.B0, g_B0);
    cudaGetSymbolAddress((void**)&p.B1, g_B1);

    // input box (normalized)
    k_init_bounds<<<(DIN + 255) / 256, 256>>>(inputs, eps, p.U0, p.L0);

    // ---- layer 1 ----
    // affine bounds (the first back-substitution is arithmetically identical)
    k_affine_interval<<<H, 256>>>(p.w1, p.b1, p.U0, p.L0, p.UBL + 0 * H, p.LBL + 0 * H, DIN);
    k_spu<<<(H + 255) / 256, 256>>>(p.UBL + 0 * H, p.LBL + 0 * H,
                                    p.SUS + 0 * H, p.SUI + 0 * H, p.SLS + 0 * H, p.SLI + 0 * H,
                                    p.PUB + 0 * H, p.PLB + 0 * H);
    // back_sub after SPU1: diag start -> row-scale W1 -> interval
    k_rowscale<<<H, 256>>>(p.w1, p.b1, p.SUS + 0 * H, p.SUI + 0 * H, p.W1, p.B1, DIN);
    descend(p, p.W1, p.B1, H, 0, 1, p.PUB + 0 * H);
    k_rowscale<<<H, 256>>>(p.w1, p.b1, p.SLS + 0 * H, p.SLI + 0 * H, p.W1, p.B1, DIN);
    descend(p, p.W1, p.B1, H, 0, 0, p.PLB + 0 * H);

    // ---- layer 2 ----
    k_affine_interval<<<H, 256>>>(p.w2, p.b2, p.PUB + 0 * H, p.PLB + 0 * H,
                                  p.UBL + 1 * H, p.LBL + 1 * H, H);
    descend(p, p.w2, p.b2, H, 1, 1, p.UBL + 1 * H);
    descend(p, p.w2, p.b2, H, 1, 0, p.LBL + 1 * H);
    k_spu<<<(H + 255) / 256, 256>>>(p.UBL + 1 * H, p.LBL + 1 * H,
                                    p.SUS + 1 * H, p.SUI + 1 * H, p.SLS + 1 * H, p.SLI + 1 * H,
                                    p.PUB + 1 * H, p.PLB + 1 * H);
    k_rowscale<<<H, 256>>>(p.w2, p.b2, p.SUS + 1 * H, p.SUI + 1 * H, p.W1, p.B1, H);
    descend(p, p.W1, p.B1, H, 1, 1, p.PUB + 1 * H);
    k_rowscale<<<H, 256>>>(p.w2, p.b2, p.SLS + 1 * H, p.SLI + 1 * H, p.W1, p.B1, H);
    descend(p, p.W1, p.B1, H, 1, 0, p.PLB + 1 * H);

    // ---- layer 3 ----
    k_affine_interval<<<H, 256>>>(p.w3, p.b3, p.PUB + 1 * H, p.PLB + 1 * H,
                                  p.UBL + 2 * H, p.LBL + 2 * H, H);
    descend(p, p.w3, p.b3, H, 2, 1, p.UBL + 2 * H);
    descend(p, p.w3, p.b3, H, 2, 0, p.LBL + 2 * H);
    k_spu<<<(H + 255) / 256, 256>>>(p.UBL + 2 * H, p.LBL + 2 * H,
                                    p.SUS + 2 * H, p.SUI + 2 * H, p.SLS + 2 * H, p.SLI + 2 * H,
                                    p.PUB + 2 * H, p.PLB + 2 * H);
    k_rowscale<<<H, 256>>>(p.w3, p.b3, p.SUS + 2 * H, p.SUI + 2 * H, p.W1, p.B1, H);
    descend(p, p.W1, p.B1, H, 2, 1, p.PUB + 2 * H);
    k_rowscale<<<H, 256>>>(p.w3, p.b3, p.SLS + 2 * H, p.SLI + 2 * H, p.W1, p.B1, H);
    descend(p, p.W1, p.B1, H, 2, 0, p.PLB + 2 * H);

    // ---- layer 4 (only the lower bound matters for the output) ----
    k_affine_interval<<<DOUT, 256>>>(p.w4, p.b4, p.PUB + 2 * H, p.PLB + 2 * H,
                                     p.UB4, p.LB4, H);
    descend(p, p.w4, p.b4, DOUT, 3, 0, p.LB4);

    k_final_min<<<1, 32>>>(p.LB4, out);
}

// round 3
// speedup vs baseline: 1.2638x; 1.2638x over previous
#include <cuda_runtime.h>
#include <math.h>

#define H    2048
#define DIN  784
#define DOUT 10

// ---------------- scratch (device globals; no allocations allowed) ----------------
__device__ __align__(256) float g_u0[DIN], g_l0[DIN];
__device__ __align__(256) float g_ubL[3 * H], g_lbL[3 * H];   // pre-SPU bounds per hidden layer
__device__ __align__(256) float g_sus[3 * H], g_sui[3 * H];   // SPU upper slope / intercept
__device__ __align__(256) float g_sls[3 * H], g_sli[3 * H];   // SPU lower slope / intercept
__device__ __align__(256) float g_pub[3 * H], g_plb[3 * H];   // post-SPU refined bounds
__device__ __align__(256) float g_ub4[DOUT], g_lb4[DOUT];
__device__ __align__(256) float g_W0[(long)2 * H * H];        // 32 MB ping
__device__ __align__(256) float g_W1[(long)2 * H * H];        // 32 MB pong
__device__ __align__(256) float g_B0[2 * H], g_B1[2 * H];

// ---------------- device helpers ----------------
__device__ __forceinline__ float sigm_(float x) { return 1.0f / (1.0f + expf(-x)); }
__device__ __forceinline__ float spu_(float x) {
    return (x >= 0.0f) ? (x * x - 0.5f) : (sigm_(-x) - 1.0f);
}

__device__ __forceinline__ unsigned long long bcast2(float x) {
    unsigned long long r;
    unsigned u = __float_as_uint(x);
    asm("mov.b64 %0, {%1, %1};" : "=l"(r) : "r"(u));
    return r;
}
__device__ __forceinline__ void fma2(unsigned long long& d, unsigned long long a,
                                     unsigned long long b) {
    asm("fma.rn.f32x2 %0, %1, %2, %0;" : "+l"(d) : "l"(a), "l"(b));
}

__device__ __forceinline__ float block_reduce(float v) {
    __shared__ float sh[32];
    int tid = threadIdx.x;
#pragma unroll
    for (int o = 16; o > 0; o >>= 1) v += __shfl_down_sync(0xffffffffu, v, o);
    if ((tid & 31) == 0) sh[tid >> 5] = v;
    __syncthreads();
    float r = 0.0f;
    if (tid < 32) {
        int nw = ((int)blockDim.x + 31) >> 5;
        r = (tid < nw) ? sh[tid] : 0.0f;
#pragma unroll
        for (int o = 16; o > 0; o >>= 1) r += __shfl_down_sync(0xffffffffu, r, o);
    }
    __syncthreads();
    return r; // valid in tid 0
}

// ---------------- kernels ----------------
__global__ void k_init_bounds(const float* __restrict__ in, const float* __restrict__ epsp,
                              float* __restrict__ u0, float* __restrict__ l0) {
    int i = blockIdx.x * blockDim.x + threadIdx.x;
    if (i >= DIN) return;
    float e = epsp[0];
    float u = fminf(in[i] + e, 1.0f);
    float l = fmaxf(in[i] - e, 0.0f);
    u0[i] = (u - 0.1307f) / 0.3081f;
    l0[i] = (l - 0.1307f) / 0.3081f;
}

// interval bounds of W x + b given elementwise box [lb, ub]  (vectorized)
__global__ void k_affine_interval(const float* __restrict__ W, const float* __restrict__ b,
                                  const float* __restrict__ ub, const float* __restrict__ lb,
                                  float* __restrict__ uo, float* __restrict__ lo, int cols) {
    int row = blockIdx.x;
    const float4* wr = (const float4*)(W + (long)row * cols);
    const float4* u4 = (const float4*)ub;
    const float4* l4 = (const float4*)lb;
    float su = 0.0f, sl = 0.0f;
    int c4 = cols >> 2;
    for (int j = threadIdx.x; j < c4; j += blockDim.x) {
        float4 w = wr[j], u = u4[j], l = l4[j];
        float p, n;
        p = fmaxf(w.x, 0.0f); n = fminf(w.x, 0.0f); su += p * u.x + n * l.x; sl += p * l.x + n * u.x;
        p = fmaxf(w.y, 0.0f); n = fminf(w.y, 0.0f); su += p * u.y + n * l.y; sl += p * l.y + n * u.y;
        p = fmaxf(w.z, 0.0f); n = fminf(w.z, 0.0f); su += p * u.z + n * l.z; sl += p * l.z + n * u.z;
        p = fmaxf(w.w, 0.0f); n = fminf(w.w, 0.0f); su += p * u.w + n * l.w; sl += p * l.w + n * u.w;
    }
    float rs = block_reduce(su);
    float rl = block_reduce(sl);
    if (threadIdx.x == 0) { uo[row] = rs + b[row]; lo[row] = rl + b[row]; }
}

// elementwise SPU relaxation analysis (exact reference math)
__global__ void k_spu(const float* __restrict__ ub, const float* __restrict__ lb,
                      float* __restrict__ us, float* __restrict__ ui,
                      float* __restrict__ ls, float* __restrict__ li,
                      float* __restrict__ pub, float* __restrict__ plb) {
    int i = blockIdx.x * blockDim.x + threadIdx.x;
    if (i >= H) return;
    float ux = ub[i], lx = lb[i];
    float uy = spu_(ux), ly = spu_(lx);
    float sj = (uy - ly) / (ux - lx);
    float ij = uy - sj * ux;
    bool right = lx > 0.0f;
    bool left  = ux <= 0.0f;
    float mid = 0.5f * (ux + lx);
    float sp = 2.0f * mid, ip = -mid * mid - 0.5f;
    float sm = sigm_(mid);
    float ssm = -sm * (1.0f - sm), ism = -sm - ssm * mid;
    float nub = fmaxf(uy, ly);
    float nlb, usv, uiv, lsv, liv;
    if (right) {
        usv = sj; uiv = ij; lsv = sp; liv = ip; nlb = fminf(uy, ly);
    } else if (left) {
        usv = ssm; uiv = ism; lsv = sj; liv = ij; nlb = fminf(uy, ly);
    } else {
        nlb = -0.5f;
        // lower constraint (crossing)
        float spu2 = 2.0f * ux, ipu = -ux * ux - 0.5f;
        float limit = spu2 * lx + ipu;
        float clm = (fabsf(lx) > ux) ? 1.0f : 0.0f;
        float clp = sigm_((clm - 0.5f) * 10.0f) * (ly - limit) + limit;
        if (clp < -0.5f) {
            float D = 4.0f * lx * lx - 4.0f * clp - 2.0f;
            float x2 = (2.0f * lx + sqrtf(fmaxf(D, 0.0f))) * 0.5f;
            lsv = 2.0f * x2; liv = -x2 * x2 - 0.5f;
        } else {
            lsv = (-0.5f - clp) / (0.0f - lx); liv = -0.5f;
        }
        // upper constraint (crossing)
        float sl_ = sigm_(lx);
        float ssl = -sl_ * (1.0f - sl_), isl = -sl_ - ssl * lx;
        float stv = ssl * ux + isl - uy;
        if (stv > 0.0f) {
            float L = lx, R = 0.0f;
#pragma unroll
            for (int t = 0; t < 10; t++) {
                float m = 0.5f * (L + R);
                float s = sigm_(m);
                float sms = -s * (1.0f - s), ims = -s - sms * m;
                bool mask = (sms * ux + ims - uy) > 0.0f;
                L = mask ? m : L;
                R = mask ? R : m;
            }
            float scp = sigm_(-5.0f) * (L - lx) + lx;
            float sc = sigm_(scp);
            usv = -sc * (1.0f - sc);
            uiv = -sc - usv * scp;
        } else {
            usv = sj; uiv = ij;
        }
    }
    us[i] = usv; ui[i] = uiv; ls[i] = lsv; li[i] = liv;
    pub[i] = nub; plb[i] = nlb;
}

// Pass a constraint matrix through a diagonal SPU layer (sign-split column scale).
// Rows [0,Mu) are the "upper" chain, rows [Mu,M) the "lower" chain. Optional fused
// row-scale (chain start from diag SPU constraint over the source weights).
// Fuses intercept reduction + bias matvec of the next affine layer.
__global__ void k_colscale(const float* __restrict__ Wsrc, const float* __restrict__ Bsrc,
                           int srcHalf,
                           const float* __restrict__ rsu, const float* __restrict__ riu,
                           const float* __restrict__ rsl, const float* __restrict__ ril,
                           const float* __restrict__ sus, const float* __restrict__ sui,
                           const float* __restrict__ sls, const float* __restrict__ sli,
                           const float* __restrict__ blayer,
                           float* __restrict__ Wdst, float* __restrict__ Bdst, int Mu) {
    int row = blockIdx.x;
    bool up = row < Mu;
    int orow = up ? row : row - Mu;
    int srow = srcHalf ? orow : row;
    const float4* ws = (const float4*)(Wsrc + (long)srow * H);
    float4* wd = (float4*)(Wdst + (long)row * H);
    float rscale = 1.0f, bbase;
    if (rsu) {
        float ri;
        if (up) { rscale = rsu[orow]; ri = riu[orow]; }
        else    { rscale = rsl[orow]; ri = ril[orow]; }
        bbase = rscale * Bsrc[srow] + ri;
    } else {
        bbase = Bsrc[srcHalf ? srow : row];
    }
    const float4* ps = (const float4*)(up ? sus : sls);
    const float4* pi = (const float4*)(up ? sui : sli);
    const float4* ns = (const float4*)(up ? sls : sus);
    const float4* ni = (const float4*)(up ? sli : sui);
    const float4* bl = (const float4*)blayer;
    float acc = 0.0f;
    for (int j = threadIdx.x; j < H / 4; j += blockDim.x) {
        float4 w = ws[j];
        w.x *= rscale; w.y *= rscale; w.z *= rscale; w.w *= rscale;
        float4 psv = ps[j], piv = pi[j], nsv = ns[j], niv = ni[j], blv = bl[j];
        float4 o;
        float p, n;
        p = fmaxf(w.x, 0.0f); n = fminf(w.x, 0.0f); o.x = p * psv.x + n * nsv.x; acc += p * piv.x + n * niv.x + o.x * blv.x;
        p = fmaxf(w.y, 0.0f); n = fminf(w.y, 0.0f); o.y = p * psv.y + n * nsv.y; acc += p * piv.y + n * niv.y + o.y * blv.y;
        p = fmaxf(w.z, 0.0f); n = fminf(w.z, 0.0f); o.z = p * psv.z + n * nsv.z; acc += p * piv.z + n * niv.z + o.z * blv.z;
        p = fmaxf(w.w, 0.0f); n = fminf(w.w, 0.0f); o.w = p * psv.w + n * nsv.w; acc += p * piv.w + n * niv.w + o.w * blv.w;
        wd[j] = o;
    }
    float r = block_reduce(acc);
    if (threadIdx.x == 0) Bdst[row] = bbase + r;
}

// Final interval evaluation at the input layer + bound refinement.
// Rows [0,Mu): upper (min-refine ubio[orow]); rows [Mu,M): lower (max-refine lbio[orow]).
// Optional fused row-scale (used when the chain has zero GEMM steps).
__global__ void k_interval_f(const float* __restrict__ W, const float* __restrict__ bvec,
                             int srcHalf,
                             const float* __restrict__ rsu, const float* __restrict__ riu,
                             const float* __restrict__ rsl, const float* __restrict__ ril,
                             const float* __restrict__ u0, const float* __restrict__ l0,
                             float* __restrict__ ubio, float* __restrict__ lbio,
                             int cols, int Mu) {
    int row = blockIdx.x;
    bool up = row < Mu;
    int orow = up ? row : row - Mu;
    int srow = srcHalf ? orow : row;
    const float4* wr = (const float4*)(W + (long)srow * cols);
    float rscale = 1.0f, rint = 0.0f;
    if (rsu) {
        if (up) { rscale = rsu[orow]; rint = riu[orow]; }
        else    { rscale = rsl[orow]; rint = ril[orow]; }
    }
    const float4* a4 = (const float4*)(up ? u0 : l0);
    const float4* c4p = (const float4*)(up ? l0 : u0);
    float acc = 0.0f;
    for (int j = threadIdx.x; j < cols / 4; j += blockDim.x) {
        float4 w = wr[j];
        w.x *= rscale; w.y *= rscale; w.z *= rscale; w.w *= rscale;
        float4 av = a4[j], cv = c4p[j];
        acc += fmaxf(w.x, 0.0f) * av.x + fminf(w.x, 0.0f) * cv.x;
        acc += fmaxf(w.y, 0.0f) * av.y + fminf(w.y, 0.0f) * cv.y;
        acc += fmaxf(w.z, 0.0f) * av.z + fminf(w.z, 0.0f) * cv.z;
        acc += fmaxf(w.w, 0.0f) * av.w + fminf(w.w, 0.0f) * cv.w;
    }
    float r = block_reduce(acc);
    if (threadIdx.x == 0) {
        float v = r + (rsu ? (rscale * bvec[srow] + rint) : bvec[row]);
        if (up) ubio[orow] = fminf(ubio[orow], v);
        else    lbio[orow] = fmaxf(lbio[orow], v);
    }
}

// SGEMM with packed f32x2 FMAs: C[MxN] = A[MxK] @ B[KxN], row-major, K%8==0, N%4==0
#define BM 128
#define BN 128
#define BK 8
__global__ __launch_bounds__(256) void sgemm(const float* __restrict__ A,
                                             const float* __restrict__ B,
                                             float* __restrict__ C,
                                             int M, int N, int K) {
    __shared__ __align__(16) float As[BK][BM + 4];
    __shared__ __align__(16) float Bs[BK][BN];
    int tid = threadIdx.x;
    int tx = tid & 15, ty = tid >> 4;
    int rowBase = blockIdx.y * BM;
    int colBase = blockIdx.x * BN;

    unsigned long long acc2[8][4];
#pragma unroll
    for (int m = 0; m < 8; m++)
#pragma unroll
        for (int np = 0; np < 4; np++) acc2[m][np] = 0ull;

    int ar = tid >> 1, ac4 = (tid & 1) * 4;       // A tile: 128 rows x 8 cols
    int br = tid >> 5, bc4 = (tid & 31) * 4;      // B tile: 8 rows x 128 cols

    for (int k0 = 0; k0 < K; k0 += BK) {
        {
            int gr = rowBase + ar;
            float4 v = make_float4(0.f, 0.f, 0.f, 0.f);
            if (gr < M) v = *(const float4*)(A + (long)gr * K + k0 + ac4);
            As[ac4 + 0][ar] = v.x; As[ac4 + 1][ar] = v.y;
            As[ac4 + 2][ar] = v.z; As[ac4 + 3][ar] = v.w;
        }
        {
            int gc = colBase + bc4;
            float4 v = make_float4(0.f, 0.f, 0.f, 0.f);
            if (gc < N) v = *(const float4*)(B + (long)(k0 + br) * N + gc);
            *(float4*)(&Bs[br][bc4]) = v;
        }
        __syncthreads();
#pragma unroll
        for (int kk = 0; kk < BK; kk++) {
            float a[8];
            unsigned long long b2[4];
#pragma unroll
            for (int i = 0; i < 4; i++)
                *(float2*)(a + 2 * i) = *(const float2*)(&As[kk][ty * 8 + 2 * i]);
#pragma unroll
            for (int np = 0; np < 4; np++)
                b2[np] = *(const unsigned long long*)(&Bs[kk][tx * 8 + 2 * np]);
#pragma unroll
            for (int m = 0; m < 8; m++) {
                unsigned long long am = bcast2(a[m]);
#pragma unroll
                for (int np = 0; np < 4; np++) fma2(acc2[m][np], am, b2[np]);
            }
        }
        __syncthreads();
    }
#pragma unroll
    for (int m = 0; m < 8; m++) {
        int gr = rowBase + ty * 8 + m;
        if (gr >= M) continue;
#pragma unroll
        for (int np = 0; np < 4; np++) {
            int gc = colBase + tx * 8 + 2 * np;
            if (gc < N) {
                float2 v;
                v.x = __uint_as_float((unsigned)(acc2[m][np] & 0xffffffffu));
                v.y = __uint_as_float((unsigned)(acc2[m][np] >> 32));
                *(float2*)(C + (long)gr * N + gc) = v;
            }
        }
    }
}

__global__ void k_final_min(const float* __restrict__ lb4, float* __restrict__ out) {
    if (threadIdx.x == 0) {
        float m = lb4[0];
#pragma unroll
        for (int i = 1; i < DOUT; i++) m = fminf(m, lb4[i]);
        out[0] = m;
    }
}

// ---------------- host orchestration ----------------
extern "C" void kernel_launch(void* const* d_in, const int* in_sizes, int n_in,
                              void* d_out, int out_size) {
    (void)in_sizes; (void)n_in; (void)out_size;
    const float* inputs = (const float*)d_in[0];
    const float* eps    = (const float*)d_in[1];
    const float* w1 = (const float*)d_in[2]; const float* b1 = (const float*)d_in[3];
    const float* w2 = (const float*)d_in[4]; const float* b2 = (const float*)d_in[5];
    const float* w3 = (const float*)d_in[6]; const float* b3 = (const float*)d_in[7];
    const float* w4 = (const float*)d_in[8]; const float* b4 = (const float*)d_in[9];
    float* out = (float*)d_out;

    float *U0, *L0, *UBL, *LBL, *SUS, *SUI, *SLS, *SLI, *PUB, *PLB, *UB4, *LB4;
    float *W0, *W1b, *B0, *B1;
    cudaGetSymbolAddress((void**)&U0, g_u0);
    cudaGetSymbolAddress((void**)&L0, g_l0);
    cudaGetSymbolAddress((void**)&UBL, g_ubL);
    cudaGetSymbolAddress((void**)&LBL, g_lbL);
    cudaGetSymbolAddress((void**)&SUS, g_sus);
    cudaGetSymbolAddress((void**)&SUI, g_sui);
    cudaGetSymbolAddress((void**)&SLS, g_sls);
    cudaGetSymbolAddress((void**)&SLI, g_sli);
    cudaGetSymbolAddress((void**)&PUB, g_pub);
    cudaGetSymbolAddress((void**)&PLB, g_plb);
    cudaGetSymbolAddress((void**)&UB4, g_ub4);
    cudaGetSymbolAddress((void**)&LB4, g_lb4);
    cudaGetSymbolAddress((void**)&W0, g_W0);
    cudaGetSymbolAddress((void**)&W1b, g_W1);
    cudaGetSymbolAddress((void**)&B0, g_B0);
    cudaGetSymbolAddress((void**)&B1, g_B1);

    const float* LW[3]  = {w1, w2, w3};
    const float* LBv[3] = {b1, b2, b3};

    auto gemm = [&](const float* A, const float* Bm, float* C, int M, int N, int K) {
        dim3 g((N + BN - 1) / BN, (M + BM - 1) / BM);
        sgemm<<<g, 256>>>(A, Bm, C, M, N, K);
    };

    // Batched descend: constraint rows [0,Mu) upper, [Mu,M) lower, over post-SPU
    // vars of hidden layer lvl (1-based; SPU arrays are 0-based lvl-1).
    // Start is either a raw weight matrix (srcHalf=1, optional fused rowscale) or
    // a full big matrix. Ends with interval refinement of (ubio, lbio).
    auto descend = [&](const float* sW, const float* sB, int srcHalf,
                       const float* rsu, const float* riu, const float* rsl, const float* ril,
                       int M, int Mu, int lvl, float* ubio, float* lbio) {
        const float* curW = sW;
        const float* curB = sB;
        int curHalf = srcHalf;
        const float* crsu = rsu; const float* criu = riu;
        const float* crsl = rsl; const float* cril = ril;
        float* bw[2] = {W0, W1b};
        float* bb[2] = {B0, B1};
        int pw = 0, pb = 0;
        for (int l = lvl; l >= 1; --l) {
            float* tW = bw[pw];
            float* tB = bb[pb];
            k_colscale<<<M, 256>>>(curW, curB, curHalf, crsu, criu, crsl, cril,
                                   SUS + (l - 1) * H, SUI + (l - 1) * H,
                                   SLS + (l - 1) * H, SLI + (l - 1) * H,
                                   LBv[l - 1], tW, tB, Mu);
            int N = (l == 1) ? DIN : H;
            float* oW = bw[pw ^ 1];
            gemm(tW, LW[l - 1], oW, M, N, H);
            curW = oW; curB = tB;
            curHalf = 0; crsu = criu = crsl = cril = nullptr;
            pw ^= 1; pb ^= 1;
        }
        k_interval_f<<<M, 256>>>(curW, curB, curHalf, crsu, criu, crsl, cril,
                                 U0, L0, ubio, lbio, DIN, Mu);
    };

    // input box (normalized)
    k_init_bounds<<<(DIN + 255) / 256, 256>>>(inputs, eps, U0, L0);

    // ---- layer 1 ----
    k_affine_interval<<<H, 256>>>(w1, b1, U0, L0, UBL + 0 * H, LBL + 0 * H, DIN);
    k_spu<<<(H + 255) / 256, 256>>>(UBL + 0 * H, LBL + 0 * H,
                                    SUS + 0 * H, SUI + 0 * H, SLS + 0 * H, SLI + 0 * H,
                                    PUB + 0 * H, PLB + 0 * H);
    // post-SPU1 refinement: zero GEMM steps -> fused rowscale+interval, batched
    k_interval_f<<<2 * H, 256>>>(w1, b1, 1,
                                 SUS + 0 * H, SUI + 0 * H, SLS + 0 * H, SLI + 0 * H,
                                 U0, L0, PUB + 0 * H, PLB + 0 * H, DIN, H);

    // ---- layer 2 ----
    k_affine_interval<<<H, 256>>>(w2, b2, PUB + 0 * H, PLB + 0 * H,
                                  UBL + 1 * H, LBL + 1 * H, H);
    descend(w2, b2, 1, nullptr, nullptr, nullptr, nullptr, 2 * H, H, 1,
            UBL + 1 * H, LBL + 1 * H);
    k_spu<<<(H + 255) / 256, 256>>>(UBL + 1 * H, LBL + 1 * H,
                                    SUS + 1 * H, SUI + 1 * H, SLS + 1 * H, SLI + 1 * H,
                                    PUB + 1 * H, PLB + 1 * H);
    descend(w2, b2, 1, SUS + 1 * H, SUI + 1 * H, SLS + 1 * H, SLI + 1 * H, 2 * H, H, 1,
            PUB + 1 * H, PLB + 1 * H);

    // ---- layer 3 ----
    k_affine_interval<<<H, 256>>>(w3, b3, PUB + 1 * H, PLB + 1 * H,
                                  UBL + 2 * H, LBL + 2 * H, H);
    descend(w3, b3, 1, nullptr, nullptr, nullptr, nullptr, 2 * H, H, 2,
            UBL + 2 * H, LBL + 2 * H);
    k_spu<<<(H + 255) / 256, 256>>>(UBL + 2 * H, LBL + 2 * H,
                                    SUS + 2 * H, SUI + 2 * H, SLS + 2 * H, SLI + 2 * H,
                                    PUB + 2 * H, PLB + 2 * H);
    descend(w3, b3, 1, SUS + 2 * H, SUI + 2 * H, SLS + 2 * H, SLI + 2 * H, 2 * H, H, 2,
            PUB + 2 * H, PLB + 2 * H);

    // ---- layer 4 (only the lower bound matters for the output) ----
    k_affine_interval<<<DOUT, 256>>>(w4, b4, PUB + 2 * H, PLB + 2 * H, UB4, LB4, H);
    descend(w4, b4, 1, nullptr, nullptr, nullptr, nullptr, DOUT, 0, 3,
            nullptr, LB4);

    k_final_min<<<1, 32>>>(LB4, out);
}

// round 6
// speedup vs baseline: 3.0393x; 2.4049x over previous
#include <cuda_runtime.h>
#include <cuda_bf16.h>
#include <cstdint>
#include <math.h>

#define H    2048
#define DIN  784
#define DOUT 10
#define NPAD1 896                 // DIN padded to a multiple of 128

// ---------------- scratch (device globals; no allocations allowed) ----------------
__device__ __align__(256) float g_u0[DIN], g_l0[DIN];
__device__ __align__(256) float g_ubL[3 * H], g_lbL[3 * H];
__device__ __align__(256) float g_sus[3 * H], g_sui[3 * H];
__device__ __align__(256) float g_sls[3 * H], g_sli[3 * H];
__device__ __align__(256) float g_pub[3 * H], g_plb[3 * H];
__device__ __align__(256) float g_ub4[DOUT], g_lb4[DOUT];
__device__ __align__(256) float g_W0[(long)2 * H * H];        // 32 MB fp32 ping
__device__ __align__(256) float g_W1[(long)2 * H * H];        // 32 MB fp32 pong
__device__ __align__(256) float g_B0[2 * H], g_B1[2 * H];
// bf16 split operand buffers
__device__ __align__(256) __nv_bfloat16 g_Ahi[(long)2 * H * H];
__device__ __align__(256) __nv_bfloat16 g_Alo[(long)2 * H * H];
__device__ __align__(256) __nv_bfloat16 g_T1hi[(long)NPAD1 * H], g_T1lo[(long)NPAD1 * H];
__device__ __align__(256) __nv_bfloat16 g_T2hi[(long)H * H],     g_T2lo[(long)H * H];
__device__ __align__(256) __nv_bfloat16 g_T3hi[(long)H * H],     g_T3lo[(long)H * H];

// ---------------- small device helpers ----------------
__device__ __forceinline__ float sigm_(float x) { return 1.0f / (1.0f + expf(-x)); }
__device__ __forceinline__ float spu_(float x) {
    return (x >= 0.0f) ? (x * x - 0.5f) : (sigm_(-x) - 1.0f);
}

__device__ __forceinline__ float block_reduce(float v) {
    __shared__ float sh[32];
    int tid = threadIdx.x;
#pragma unroll
    for (int o = 16; o > 0; o >>= 1) v += __shfl_down_sync(0xffffffffu, v, o);
    if ((tid & 31) == 0) sh[tid >> 5] = v;
    __syncthreads();
    float r = 0.0f;
    if (tid < 32) {
        int nw = ((int)blockDim.x + 31) >> 5;
        r = (tid < nw) ? sh[tid] : 0.0f;
#pragma unroll
        for (int o = 16; o > 0; o >>= 1) r += __shfl_down_sync(0xffffffffu, r, o);
    }
    __syncthreads();
    return r;
}

__device__ __forceinline__ uint32_t smem_u32(const void* p) {
    uint32_t a;
    asm("{ .reg .u64 t; cvta.to.shared.u64 t, %1; cvt.u32.u64 %0, t; }" : "=r"(a) : "l"(p));
    return a;
}
__device__ __forceinline__ void cp16(uint32_t dst, const void* src) {
    asm volatile("cp.async.cg.shared.global [%0], [%1], 16;" :: "r"(dst), "l"(src));
}
__device__ __forceinline__ void mma16816(float* d, const uint32_t* a, const uint32_t* b) {
    asm volatile(
        "mma.sync.aligned.m16n8k16.row.col.f32.bf16.bf16.f32 "
        "{%0,%1,%2,%3}, {%4,%5,%6,%7}, {%8,%9}, {%0,%1,%2,%3};"
        : "+f"(d[0]), "+f"(d[1]), "+f"(d[2]), "+f"(d[3])
        : "r"(a[0]), "r"(a[1]), "r"(a[2]), "r"(a[3]), "r"(b[0]), "r"(b[1]));
}

// ---------------- kernels ----------------
__global__ void k_init_bounds(const float* __restrict__ in, const float* __restrict__ epsp,
                              float* __restrict__ u0, float* __restrict__ l0) {
    int i = blockIdx.x * blockDim.x + threadIdx.x;
    if (i >= DIN) return;
    float e = epsp[0];
    float u = fminf(in[i] + e, 1.0f);
    float l = fmaxf(in[i] - e, 0.0f);
    u0[i] = (u - 0.1307f) / 0.3081f;
    l0[i] = (l - 0.1307f) / 0.3081f;
}

// transpose + bf16 split: T[n][k] = W[k][n]; rows n >= N (padding) are zero.
__global__ void k_transpose_split(const float* __restrict__ W,
                                  __nv_bfloat16* __restrict__ Thi,
                                  __nv_bfloat16* __restrict__ Tlo, int N) {
    __shared__ float t[32][33];
    int n0 = blockIdx.x * 32, k0 = blockIdx.y * 32;
    int tx = threadIdx.x, ty = threadIdx.y;
#pragma unroll
    for (int i = 0; i < 4; i++) {
        int k = k0 + ty + 8 * i;
        int n = n0 + tx;
        t[ty + 8 * i][tx] = (n < N) ? W[(long)k * N + n] : 0.0f;
    }
    __syncthreads();
#pragma unroll
    for (int i = 0; i < 4; i++) {
        int n = n0 + ty + 8 * i;
        int k = k0 + tx;
        float v = t[tx][ty + 8 * i];
        __nv_bfloat16 hi = __float2bfloat16(v);
        __nv_bfloat16 lo = __float2bfloat16(v - __bfloat162float(hi));
        Thi[(long)n * H + k] = hi;
        Tlo[(long)n * H + k] = lo;
    }
}

// interval bounds of W x + b given elementwise box [lb, ub]
__global__ void k_affine_interval(const float* __restrict__ W, const float* __restrict__ b,
                                  const float* __restrict__ ub, const float* __restrict__ lb,
                                  float* __restrict__ uo, float* __restrict__ lo, int cols) {
    int row = blockIdx.x;
    const float4* wr = (const float4*)(W + (long)row * cols);
    const float4* u4 = (const float4*)ub;
    const float4* l4 = (const float4*)lb;
    float su = 0.0f, sl = 0.0f;
    int c4 = cols >> 2;
    for (int j = threadIdx.x; j < c4; j += blockDim.x) {
        float4 w = wr[j], u = u4[j], l = l4[j];
        float p, n;
        p = fmaxf(w.x, 0.0f); n = fminf(w.x, 0.0f); su += p * u.x + n * l.x; sl += p * l.x + n * u.x;
        p = fmaxf(w.y, 0.0f); n = fminf(w.y, 0.0f); su += p * u.y + n * l.y; sl += p * l.y + n * u.y;
        p = fmaxf(w.z, 0.0f); n = fminf(w.z, 0.0f); su += p * u.z + n * l.z; sl += p * l.z + n * u.z;
        p = fmaxf(w.w, 0.0f); n = fminf(w.w, 0.0f); su += p * u.w + n * l.w; sl += p * l.w + n * u.w;
    }
    float rs = block_reduce(su);
    float rl = block_reduce(sl);
    if (threadIdx.x == 0) { uo[row] = rs + b[row]; lo[row] = rl + b[row]; }
}

// elementwise SPU relaxation analysis (exact reference math)
__global__ void k_spu(const float* __restrict__ ub, const float* __restrict__ lb,
                      float* __restrict__ us, float* __restrict__ ui,
                      float* __restrict__ ls, float* __restrict__ li,
                      float* __restrict__ pub, float* __restrict__ plb) {
    int i = blockIdx.x * blockDim.x + threadIdx.x;
    if (i >= H) return;
    float ux = ub[i], lx = lb[i];
    float uy = spu_(ux), ly = spu_(lx);
    float sj = (uy - ly) / (ux - lx);
    float ij = uy - sj * ux;
    bool right = lx > 0.0f;
    bool left  = ux <= 0.0f;
    float mid = 0.5f * (ux + lx);
    float sp = 2.0f * mid, ip = -mid * mid - 0.5f;
    float sm = sigm_(mid);
    float ssm = -sm * (1.0f - sm), ism = -sm - ssm * mid;
    float nub = fmaxf(uy, ly);
    float nlb, usv, uiv, lsv, liv;
    if (right) {
        usv = sj; uiv = ij; lsv = sp; liv = ip; nlb = fminf(uy, ly);
    } else if (left) {
        usv = ssm; uiv = ism; lsv = sj; liv = ij; nlb = fminf(uy, ly);
    } else {
        nlb = -0.5f;
        float spu2 = 2.0f * ux, ipu = -ux * ux - 0.5f;
        float limit = spu2 * lx + ipu;
        float clm = (fabsf(lx) > ux) ? 1.0f : 0.0f;
        float clp = sigm_((clm - 0.5f) * 10.0f) * (ly - limit) + limit;
        if (clp < -0.5f) {
            float D = 4.0f * lx * lx - 4.0f * clp - 2.0f;
            float x2 = (2.0f * lx + sqrtf(fmaxf(D, 0.0f))) * 0.5f;
            lsv = 2.0f * x2; liv = -x2 * x2 - 0.5f;
        } else {
            lsv = (-0.5f - clp) / (0.0f - lx); liv = -0.5f;
        }
        float sl_ = sigm_(lx);
        float ssl = -sl_ * (1.0f - sl_), isl = -sl_ - ssl * lx;
        float stv = ssl * ux + isl - uy;
        if (stv > 0.0f) {
            float L = lx, R = 0.0f;
#pragma unroll
            for (int t = 0; t < 10; t++) {
                float m = 0.5f * (L + R);
                float s = sigm_(m);
                float sms = -s * (1.0f - s), ims = -s - sms * m;
                bool mask = (sms * ux + ims - uy) > 0.0f;
                L = mask ? m : L;
                R = mask ? R : m;
            }
            float scp = sigm_(-5.0f) * (L - lx) + lx;
            float sc = sigm_(scp);
            usv = -sc * (1.0f - sc);
            uiv = -sc - usv * scp;
        } else {
            usv = sj; uiv = ij;
        }
    }
    us[i] = usv; ui[i] = uiv; ls[i] = lsv; li[i] = liv;
    pub[i] = nub; plb[i] = nlb;
}

// Column-scale through a diagonal SPU layer, emitting bf16 hi/lo A operands.
__global__ void k_colscale(const float* __restrict__ Wsrc, const float* __restrict__ Bsrc,
                           int srcHalf,
                           const float* __restrict__ rsu, const float* __restrict__ riu,
                           const float* __restrict__ rsl, const float* __restrict__ ril,
                           const float* __restrict__ sus, const float* __restrict__ sui,
                           const float* __restrict__ sls, const float* __restrict__ sli,
                           const float* __restrict__ blayer,
                           __nv_bfloat16* __restrict__ Ahi, __nv_bfloat16* __restrict__ Alo,
                           float* __restrict__ Bdst, int Mu) {
    int row = blockIdx.x;
    bool up = row < Mu;
    int orow = up ? row : row - Mu;
    int srow = srcHalf ? orow : row;
    const float4* ws = (const float4*)(Wsrc + (long)srow * H);
    __nv_bfloat162* ah = (__nv_bfloat162*)(Ahi + (long)row * H);
    __nv_bfloat162* al = (__nv_bfloat162*)(Alo + (long)row * H);
    float rscale = 1.0f, bbase;
    if (rsu) {
        float ri;
        if (up) { rscale = rsu[orow]; ri = riu[orow]; }
        else    { rscale = rsl[orow]; ri = ril[orow]; }
        bbase = rscale * Bsrc[srow] + ri;
    } else {
        bbase = Bsrc[row];
    }
    const float4* ps = (const float4*)(up ? sus : sls);
    const float4* pi = (const float4*)(up ? sui : sli);
    const float4* ns = (const float4*)(up ? sls : sus);
    const float4* ni = (const float4*)(up ? sli : sui);
    const float4* bl = (const float4*)blayer;
    float acc = 0.0f;
    for (int j = threadIdx.x; j < H / 4; j += blockDim.x) {
        float4 w = ws[j];
        w.x *= rscale; w.y *= rscale; w.z *= rscale; w.w *= rscale;
        float4 psv = ps[j], piv = pi[j], nsv = ns[j], niv = ni[j], blv = bl[j];
        float4 o;
        float p, n;
        p = fmaxf(w.x, 0.0f); n = fminf(w.x, 0.0f); o.x = p * psv.x + n * nsv.x; acc += p * piv.x + n * niv.x + o.x * blv.x;
        p = fmaxf(w.y, 0.0f); n = fminf(w.y, 0.0f); o.y = p * psv.y + n * nsv.y; acc += p * piv.y + n * niv.y + o.y * blv.y;
        p = fmaxf(w.z, 0.0f); n = fminf(w.z, 0.0f); o.z = p * psv.z + n * nsv.z; acc += p * piv.z + n * niv.z + o.z * blv.z;
        p = fmaxf(w.w, 0.0f); n = fminf(w.w, 0.0f); o.w = p * psv.w + n * nsv.w; acc += p * piv.w + n * niv.w + o.w * blv.w;
        __nv_bfloat16 hx = __float2bfloat16(o.x), hy = __float2bfloat16(o.y);
        __nv_bfloat16 hz = __float2bfloat16(o.z), hw = __float2bfloat16(o.w);
        __nv_bfloat16 lx = __float2bfloat16(o.x - __bfloat162float(hx));
        __nv_bfloat16 ly = __float2bfloat16(o.y - __bfloat162float(hy));
        __nv_bfloat16 lz = __float2bfloat16(o.z - __bfloat162float(hz));
        __nv_bfloat16 lw = __float2bfloat16(o.w - __bfloat162float(hw));
        ah[2 * j]     = __halves2bfloat162(hx, hy);
        ah[2 * j + 1] = __halves2bfloat162(hz, hw);
        al[2 * j]     = __halves2bfloat162(lx, ly);
        al[2 * j + 1] = __halves2bfloat162(lz, lw);
    }
    float r = block_reduce(acc);
    if (threadIdx.x == 0) Bdst[row] = bbase + r;
}

// Final interval evaluation at the input layer + bound refinement.
__global__ void k_interval_f(const float* __restrict__ W, int ld,
                             const float* __restrict__ bvec, int srcHalf,
                             const float* __restrict__ rsu, const float* __restrict__ riu,
                             const float* __restrict__ rsl, const float* __restrict__ ril,
                             const float* __restrict__ u0, const float* __restrict__ l0,
                             float* __restrict__ ubio, float* __restrict__ lbio,
                             int cols, int Mu) {
    int row = blockIdx.x;
    bool up = row < Mu;
    int orow = up ? row : row - Mu;
    int srow = srcHalf ? orow : row;
    const float4* wr = (const float4*)(W + (long)srow * ld);
    float rscale = 1.0f, rint = 0.0f;
    if (rsu) {
        if (up) { rscale = rsu[orow]; rint = riu[orow]; }
        else    { rscale = rsl[orow]; rint = ril[orow]; }
    }
    const float4* a4 = (const float4*)(up ? u0 : l0);
    const float4* c4p = (const float4*)(up ? l0 : u0);
    float acc = 0.0f;
    for (int j = threadIdx.x; j < cols / 4; j += blockDim.x) {
        float4 w = wr[j];
        w.x *= rscale; w.y *= rscale; w.z *= rscale; w.w *= rscale;
        float4 av = a4[j], cv = c4p[j];
        acc += fmaxf(w.x, 0.0f) * av.x + fminf(w.x, 0.0f) * cv.x;
        acc += fmaxf(w.y, 0.0f) * av.y + fminf(w.y, 0.0f) * cv.y;
        acc += fmaxf(w.z, 0.0f) * av.z + fminf(w.z, 0.0f) * cv.z;
        acc += fmaxf(w.w, 0.0f) * av.w + fminf(w.w, 0.0f) * cv.w;
    }
    float r = block_reduce(acc);
    if (threadIdx.x == 0) {
        float v = r + (rsu ? (rscale * bvec[srow] + rint) : bvec[row]);
        if (up) ubio[orow] = fminf(ubio[orow], v);
        else    lbio[orow] = fmaxf(lbio[orow], v);
    }
}

// ---------------- bf16-split GEMM via mma.sync (HMMA; baseline PTX feature) ----------------
// C[M x Npad] = (Ahi+Alo)[M x 2048] @ (Bhi+Blo)^T, B stored [Npad x 2048] K-major.
// 3-term split: Ahi*Bhi + Ahi*Blo + Alo*Bhi, fp32 accumulate.
// CTA tile 128x128, 8 warps (2x4), warp tile 64x32, BK=32, cp.async double buffer.
#define GSTRIDE 80                 // smem row stride in bytes (32 bf16 + pad) — conflict-free
#define TILEB   (128 * GSTRIDE)    // 10240 bytes per matrix tile
#define STAGEB  (4 * TILEB)        // 40960 bytes per stage
#define GEMM_SMEM (2 * STAGEB)     // 81920

__global__ __launch_bounds__(256) void gemm_mma(
    const __nv_bfloat16* __restrict__ Ahi, const __nv_bfloat16* __restrict__ Alo,
    const __nv_bfloat16* __restrict__ Bhi, const __nv_bfloat16* __restrict__ Blo,
    float* __restrict__ C, int M, int ldc) {
    extern __shared__ char dynsm[];
    const int tid = threadIdx.x;
    const int wid = tid >> 5;
    const int lane = tid & 31;
    const int rowBase = blockIdx.y * 128;
    const int colBase = blockIdx.x * 128;
    const uint32_t smbase = smem_u32(dynsm);

    const int wm = wid & 1, wn = wid >> 1;         // warp grid 2 x 4
    const int mbase = wm * 64, nbase = wn * 32;
    const int lr = lane >> 2, lc2 = 2 * (lane & 3);

    float acc[4][4][4];
#pragma unroll
    for (int mi = 0; mi < 4; mi++)
#pragma unroll
        for (int ni = 0; ni < 4; ni++)
#pragma unroll
            for (int t = 0; t < 4; t++) acc[mi][ni][t] = 0.0f;

    // issue cp.async loads for k-chunk c into stage c&1
    auto issue = [&](int c) {
        const int st = c & 1;
        const uint32_t base = smbase + st * STAGEB;
        const long k0 = (long)c * 32;
#pragma unroll
        for (int p = 0; p < 2; p++) {
            int u = tid + p * 256;
            int row = u >> 2, seg = u & 3;
            uint32_t so = base + row * GSTRIDE + seg * 16;
            long ka = k0 + seg * 8;
            int grow = rowBase + row; if (grow > M - 1) grow = M - 1;
            cp16(so,              Ahi + (long)grow * H + ka);
            cp16(so + TILEB,      Alo + (long)grow * H + ka);
            int gn = colBase + row;
            cp16(so + 2 * TILEB,  Bhi + (long)gn * H + ka);
            cp16(so + 3 * TILEB,  Blo + (long)gn * H + ka);
        }
        asm volatile("cp.async.commit_group;");
    };

    issue(0);
    const int NK = H / 32;   // 64
    for (int c = 0; c < NK; ++c) {
        if (c + 1 < NK) {
            issue(c + 1);
            asm volatile("cp.async.wait_group 1;");
        } else {
            asm volatile("cp.async.wait_group 0;");
        }
        __syncthreads();
        const char* sb = dynsm + (c & 1) * STAGEB;
        const char* sA = sb;
        const char* sB = sb + 2 * TILEB;
#pragma unroll
        for (int kk = 0; kk < 32; kk += 16) {
            uint32_t bh[4][2], blo[4][2];
#pragma unroll
            for (int ni = 0; ni < 4; ni++) {
                const char* p = sB + (nbase + ni * 8 + lr) * GSTRIDE + (kk + lc2) * 2;
                bh[ni][0]  = *(const uint32_t*)p;
                bh[ni][1]  = *(const uint32_t*)(p + 16);
                blo[ni][0] = *(const uint32_t*)(p + TILEB);
                blo[ni][1] = *(const uint32_t*)(p + TILEB + 16);
            }
#pragma unroll
            for (int mi = 0; mi < 4; mi++) {
                const char* q = sA + (mbase + mi * 16 + lr) * GSTRIDE + (kk + lc2) * 2;
                uint32_t ah[4], al[4];
                ah[0] = *(const uint32_t*)q;
                ah[1] = *(const uint32_t*)(q + 8 * GSTRIDE);
                ah[2] = *(const uint32_t*)(q + 16);
                ah[3] = *(const uint32_t*)(q + 8 * GSTRIDE + 16);
                al[0] = *(const uint32_t*)(q + TILEB);
                al[1] = *(const uint32_t*)(q + TILEB + 8 * GSTRIDE);
                al[2] = *(const uint32_t*)(q + TILEB + 16);
                al[3] = *(const uint32_t*)(q + TILEB + 8 * GSTRIDE + 16);
#pragma unroll
                for (int ni = 0; ni < 4; ni++) {
                    mma16816(acc[mi][ni], ah, bh[ni]);
                    mma16816(acc[mi][ni], ah, blo[ni]);
                    mma16816(acc[mi][ni], al, bh[ni]);
                }
            }
        }
        __syncthreads();
    }

#pragma unroll
    for (int mi = 0; mi < 4; mi++) {
        int gr0 = rowBase + mbase + mi * 16 + lr;
#pragma unroll
        for (int ni = 0; ni < 4; ni++) {
            int gc = colBase + nbase + ni * 8 + lc2;
            if (gr0 < M) {
                float2 v = make_float2(acc[mi][ni][0], acc[mi][ni][1]);
                *(float2*)(C + (long)gr0 * ldc + gc) = v;
            }
            if (gr0 + 8 < M) {
                float2 v = make_float2(acc[mi][ni][2], acc[mi][ni][3]);
                *(float2*)(C + (long)(gr0 + 8) * ldc + gc) = v;
            }
        }
    }
}

__global__ void k_final_min(const float* __restrict__ lb4, float* __restrict__ out) {
    if (threadIdx.x == 0) {
        float m = lb4[0];
#pragma unroll
        for (int i = 1; i < DOUT; i++) m = fminf(m, lb4[i]);
        out[0] = m;
    }
}

// ---------------- host orchestration ----------------
extern "C" void kernel_launch(void* const* d_in, const int* in_sizes, int n_in,
                              void* d_out, int out_size) {
    (void)in_sizes; (void)n_in; (void)out_size;
    const float* inputs = (const float*)d_in[0];
    const float* eps    = (const float*)d_in[1];
    const float* w1 = (const float*)d_in[2]; const float* b1 = (const float*)d_in[3];
    const float* w2 = (const float*)d_in[4]; const float* b2 = (const float*)d_in[5];
    const float* w3 = (const float*)d_in[6]; const float* b3 = (const float*)d_in[7];
    const float* w4 = (const float*)d_in[8]; const float* b4 = (const float*)d_in[9];
    float* out = (float*)d_out;

    cudaFuncSetAttribute(gemm_mma, cudaFuncAttributeMaxDynamicSharedMemorySize, GEMM_SMEM);

    float *U0, *L0, *UBL, *LBL, *SUS, *SUI, *SLS, *SLI, *PUB, *PLB, *UB4, *LB4;
    float *W0, *W1b, *B0, *B1;
    __nv_bfloat16 *AHI, *ALO, *T1H, *T1L, *T2H, *T2L, *T3H, *T3L;
    cudaGetSymbolAddress((void**)&U0, g_u0);
    cudaGetSymbolAddress((void**)&L0, g_l0);
    cudaGetSymbolAddress((void**)&UBL, g_ubL);
    cudaGetSymbolAddress((void**)&LBL, g_lbL);
    cudaGetSymbolAddress((void**)&SUS, g_sus);
    cudaGetSymbolAddress((void**)&SUI, g_sui);
    cudaGetSymbolAddress((void**)&SLS, g_sls);
    cudaGetSymbolAddress((void**)&SLI, g_sli);
    cudaGetSymbolAddress((void**)&PUB, g_pub);
    cudaGetSymbolAddress((void**)&PLB, g_plb);
    cudaGetSymbolAddress((void**)&UB4, g_ub4);
    cudaGetSymbolAddress((void**)&LB4, g_lb4);
    cudaGetSymbolAddress((void**)&W0, g_W0);
    cudaGetSymbolAddress((void**)&W1b, g_W1);
    cudaGetSymbolAddress((void**)&B0, g_B0);
    cudaGetSymbolAddress((void**)&B1, g_B1);
    cudaGetSymbolAddress((void**)&AHI, g_Ahi);
    cudaGetSymbolAddress((void**)&ALO, g_Alo);
    cudaGetSymbolAddress((void**)&T1H, g_T1hi);
    cudaGetSymbolAddress((void**)&T1L, g_T1lo);
    cudaGetSymbolAddress((void**)&T2H, g_T2hi);
    cudaGetSymbolAddress((void**)&T2L, g_T2lo);
    cudaGetSymbolAddress((void**)&T3H, g_T3hi);
    cudaGetSymbolAddress((void**)&T3L, g_T3lo);

    const float* LBv[3] = {b1, b2, b3};
    const __nv_bfloat16* TH[3] = {T1H, T2H, T3H};
    const __nv_bfloat16* TL[3] = {T1L, T2L, T3L};

    // transposed + split weights (B operands)
    k_transpose_split<<<dim3(NPAD1 / 32, H / 32), dim3(32, 8)>>>(w1, T1H, T1L, DIN);
    k_transpose_split<<<dim3(H / 32, H / 32),     dim3(32, 8)>>>(w2, T2H, T2L, H);
    k_transpose_split<<<dim3(H / 32, H / 32),     dim3(32, 8)>>>(w3, T3H, T3L, H);

    auto descend = [&](const float* sW, const float* sB, int srcHalf,
                       const float* rsu, const float* riu, const float* rsl, const float* ril,
                       int M, int Mu, int lvl, float* ubio, float* lbio) {
        const float* curW = sW;
        const float* curB = sB;
        int curHalf = srcHalf;
        const float* crsu = rsu; const float* criu = riu;
        const float* crsl = rsl; const float* cril = ril;
        float* bw[2] = {W0, W1b};
        float* bb[2] = {B0, B1};
        int pw = 0, pb = 0;
        int curLd = H;
        for (int l = lvl; l >= 1; --l) {
            float* tB = bb[pb];
            k_colscale<<<M, 256>>>(curW, curB, curHalf, crsu, criu, crsl, cril,
                                   SUS + (l - 1) * H, SUI + (l - 1) * H,
                                   SLS + (l - 1) * H, SLI + (l - 1) * H,
                                   LBv[l - 1], AHI, ALO, tB, Mu);
            int Npad = (l == 1) ? NPAD1 : H;
            float* oW = bw[pw];
            dim3 g(Npad / 128, (M + 127) / 128);
            gemm_mma<<<g, 256, GEMM_SMEM>>>(AHI, ALO, TH[l - 1], TL[l - 1], oW, M, Npad);
            curW = oW; curB = tB;
            curHalf = 0; crsu = criu = crsl = cril = nullptr;
            pw ^= 1; pb ^= 1;
            curLd = Npad;
        }
        k_interval_f<<<M, 256>>>(curW, curLd, curB, curHalf, crsu, criu, crsl, cril,
                                 U0, L0, ubio, lbio, DIN, Mu);
    };

    // input box (normalized)
    k_init_bounds<<<(DIN + 255) / 256, 256>>>(inputs, eps, U0, L0);

    // ---- layer 1 ----
    k_affine_interval<<<H, 256>>>(w1, b1, U0, L0, UBL + 0 * H, LBL + 0 * H, DIN);
    k_spu<<<(H + 255) / 256, 256>>>(UBL + 0 * H, LBL + 0 * H,
                                    SUS + 0 * H, SUI + 0 * H, SLS + 0 * H, SLI + 0 * H,
                                    PUB + 0 * H, PLB + 0 * H);
    k_interval_f<<<2 * H, 256>>>(w1, DIN, b1, 1,
                                 SUS + 0 * H, SUI + 0 * H, SLS + 0 * H, SLI + 0 * H,
                                 U0, L0, PUB + 0 * H, PLB + 0 * H, DIN, H);

    // ---- layer 2 ----
    k_affine_interval<<<H, 256>>>(w2, b2, PUB + 0 * H, PLB + 0 * H,
                                  UBL + 1 * H, LBL + 1 * H, H);
    descend(w2, b2, 1, nullptr, nullptr, nullptr, nullptr, 2 * H, H, 1,
            UBL + 1 * H, LBL + 1 * H);
    k_spu<<<(H + 255) / 256, 256>>>(UBL + 1 * H, LBL + 1 * H,
                                    SUS + 1 * H, SUI + 1 * H, SLS + 1 * H, SLI + 1 * H,
                                    PUB + 1 * H, PLB + 1 * H);
    descend(w2, b2, 1, SUS + 1 * H, SUI + 1 * H, SLS + 1 * H, SLI + 1 * H, 2 * H, H, 1,
            PUB + 1 * H, PLB + 1 * H);

    // ---- layer 3 ----
    k_affine_interval<<<H, 256>>>(w3, b3, PUB + 1 * H, PLB + 1 * H,
                                  UBL + 2 * H, LBL + 2 * H, H);
    descend(w3, b3, 1, nullptr, nullptr, nullptr, nullptr, 2 * H, H, 2,
            UBL + 2 * H, LBL + 2 * H);
    k_spu<<<(H + 255) / 256, 256>>>(UBL + 2 * H, LBL + 2 * H,
                                    SUS + 2 * H, SUI + 2 * H, SLS + 2 * H, SLI + 2 * H,
                                    PUB + 2 * H, PLB + 2 * H);
    descend(w3, b3, 1, SUS + 2 * H, SUI + 2 * H, SLS + 2 * H, SLI + 2 * H, 2 * H, H, 2,
            PUB + 2 * H, PLB + 2 * H);

    // ---- layer 4 (only the lower bound matters for the output) ----
    k_affine_interval<<<DOUT, 256>>>(w4, b4, PUB + 2 * H, PLB + 2 * H, UB4, LB4, H);
    descend(w4, b4, 1, nullptr, nullptr, nullptr, nullptr, DOUT, 0, 3, nullptr, LB4);

    k_final_min<<<1, 32>>>(LB4, out);
}

// round 7
// speedup vs baseline: 5.1498x; 1.6944x over previous
#include <cuda_runtime.h>
#include <cuda_bf16.h>
#include <cstdint>
#include <math.h>

#define H    2048
#define DIN  784
#define DOUT 10
#define NPAD1 896                 // DIN padded to a multiple of 128

// ---------------- scratch (device globals; no allocations allowed) ----------------
__device__ __align__(256) float g_u0[DIN], g_l0[DIN];
__device__ __align__(256) float g_ubL[3 * H], g_lbL[3 * H];
__device__ __align__(256) float g_sus[3 * H], g_sui[3 * H];
__device__ __align__(256) float g_sls[3 * H], g_sli[3 * H];
__device__ __align__(256) float g_pub[3 * H], g_plb[3 * H];
__device__ __align__(256) float g_ub4[DOUT], g_lb4[DOUT];
__device__ __align__(256) float g_rawV[2 * H];                // raw descended values (u | l)
__device__ __align__(256) float g_W0[(long)2 * H * H];        // 32 MB fp32 ping
__device__ __align__(256) float g_W1[(long)2 * H * H];        // 32 MB fp32 pong
__device__ __align__(256) float g_B0[2 * H], g_B1[2 * H];
// bf16 split operand buffers
__device__ __align__(256) __nv_bfloat16 g_Ahi[(long)2 * H * H];
__device__ __align__(256) __nv_bfloat16 g_Alo[(long)2 * H * H];
__device__ __align__(256) __nv_bfloat16 g_T1hi[(long)NPAD1 * H], g_T1lo[(long)NPAD1 * H];
__device__ __align__(256) __nv_bfloat16 g_T2hi[(long)H * H],     g_T2lo[(long)H * H];
__device__ __align__(256) __nv_bfloat16 g_T3hi[(long)H * H],     g_T3lo[(long)H * H];

// ---------------- small device helpers ----------------
__device__ __forceinline__ float sigm_(float x) { return 1.0f / (1.0f + expf(-x)); }
__device__ __forceinline__ float spu_(float x) {
    return (x >= 0.0f) ? (x * x - 0.5f) : (sigm_(-x) - 1.0f);
}

__device__ __forceinline__ float block_reduce(float v) {
    __shared__ float sh[32];
    int tid = threadIdx.x;
#pragma unroll
    for (int o = 16; o > 0; o >>= 1) v += __shfl_down_sync(0xffffffffu, v, o);
    if ((tid & 31) == 0) sh[tid >> 5] = v;
    __syncthreads();
    float r = 0.0f;
    if (tid < 32) {
        int nw = ((int)blockDim.x + 31) >> 5;
        r = (tid < nw) ? sh[tid] : 0.0f;
#pragma unroll
        for (int o = 16; o > 0; o >>= 1) r += __shfl_down_sync(0xffffffffu, r, o);
    }
    __syncthreads();
    return r;
}

__device__ __forceinline__ uint32_t smem_u32(const void* p) {
    uint32_t a;
    asm("{ .reg .u64 t; cvta.to.shared.u64 t, %1; cvt.u32.u64 %0, t; }" : "=r"(a) : "l"(p));
    return a;
}
__device__ __forceinline__ void cp16(uint32_t dst, const void* src) {
    asm volatile("cp.async.cg.shared.global [%0], [%1], 16;" :: "r"(dst), "l"(src));
}
__device__ __forceinline__ void mma16816(float* d, const uint32_t* a, const uint32_t* b) {
    asm volatile(
        "mma.sync.aligned.m16n8k16.row.col.f32.bf16.bf16.f32 "
        "{%0,%1,%2,%3}, {%4,%5,%6,%7}, {%8,%9}, {%0,%1,%2,%3};"
        : "+f"(d[0]), "+f"(d[1]), "+f"(d[2]), "+f"(d[3])
        : "r"(a[0]), "r"(a[1]), "r"(a[2]), "r"(a[3]), "r"(b[0]), "r"(b[1]));
}

// ---------------- kernels ----------------
__global__ void k_init_bounds(const float* __restrict__ in, const float* __restrict__ epsp,
                              float* __restrict__ u0, float* __restrict__ l0) {
    int i = blockIdx.x * blockDim.x + threadIdx.x;
    if (i >= DIN) return;
    float e = epsp[0];
    float u = fminf(in[i] + e, 1.0f);
    float l = fmaxf(in[i] - e, 0.0f);
    u0[i] = (u - 0.1307f) / 0.3081f;
    l0[i] = (l - 0.1307f) / 0.3081f;
}

// transpose + bf16 split: T[n][k] = W[k][n]; rows n >= N (padding) are zero.
__global__ void k_transpose_split(const float* __restrict__ W,
                                  __nv_bfloat16* __restrict__ Thi,
                                  __nv_bfloat16* __restrict__ Tlo, int N) {
    __shared__ float t[32][33];
    int n0 = blockIdx.x * 32, k0 = blockIdx.y * 32;
    int tx = threadIdx.x, ty = threadIdx.y;
#pragma unroll
    for (int i = 0; i < 4; i++) {
        int k = k0 + ty + 8 * i;
        int n = n0 + tx;
        t[ty + 8 * i][tx] = (n < N) ? W[(long)k * N + n] : 0.0f;
    }
    __syncthreads();
#pragma unroll
    for (int i = 0; i < 4; i++) {
        int n = n0 + ty + 8 * i;
        int k = k0 + tx;
        float v = t[tx][ty + 8 * i];
        __nv_bfloat16 hi = __float2bfloat16(v);
        __nv_bfloat16 lo = __float2bfloat16(v - __bfloat162float(hi));
        Thi[(long)n * H + k] = hi;
        Tlo[(long)n * H + k] = lo;
    }
}

// interval bounds of W x + b given elementwise box [lb, ub]
__global__ void k_affine_interval(const float* __restrict__ W, const float* __restrict__ b,
                                  const float* __restrict__ ub, const float* __restrict__ lb,
                                  float* __restrict__ uo, float* __restrict__ lo, int cols) {
    int row = blockIdx.x;
    const float4* wr = (const float4*)(W + (long)row * cols);
    const float4* u4 = (const float4*)ub;
    const float4* l4 = (const float4*)lb;
    float su = 0.0f, sl = 0.0f;
    int c4 = cols >> 2;
    for (int j = threadIdx.x; j < c4; j += blockDim.x) {
        float4 w = wr[j], u = u4[j], l = l4[j];
        float p, n;
        p = fmaxf(w.x, 0.0f); n = fminf(w.x, 0.0f); su += p * u.x + n * l.x; sl += p * l.x + n * u.x;
        p = fmaxf(w.y, 0.0f); n = fminf(w.y, 0.0f); su += p * u.y + n * l.y; sl += p * l.y + n * u.y;
        p = fmaxf(w.z, 0.0f); n = fminf(w.z, 0.0f); su += p * u.z + n * l.z; sl += p * l.z + n * u.z;
        p = fmaxf(w.w, 0.0f); n = fminf(w.w, 0.0f); su += p * u.w + n * l.w; sl += p * l.w + n * u.w;
    }
    float rs = block_reduce(su);
    float rl = block_reduce(sl);
    if (threadIdx.x == 0) { uo[row] = rs + b[row]; lo[row] = rl + b[row]; }
}

// elementwise SPU relaxation analysis (exact reference math)
__global__ void k_spu(const float* __restrict__ ub, const float* __restrict__ lb,
                      float* __restrict__ us, float* __restrict__ ui,
                      float* __restrict__ ls, float* __restrict__ li,
                      float* __restrict__ pub, float* __restrict__ plb) {
    int i = blockIdx.x * blockDim.x + threadIdx.x;
    if (i >= H) return;
    float ux = ub[i], lx = lb[i];
    float uy = spu_(ux), ly = spu_(lx);
    float sj = (uy - ly) / (ux - lx);
    float ij = uy - sj * ux;
    bool right = lx > 0.0f;
    bool left  = ux <= 0.0f;
    float mid = 0.5f * (ux + lx);
    float sp = 2.0f * mid, ip = -mid * mid - 0.5f;
    float sm = sigm_(mid);
    float ssm = -sm * (1.0f - sm), ism = -sm - ssm * mid;
    float nub = fmaxf(uy, ly);
    float nlb, usv, uiv, lsv, liv;
    if (right) {
        usv = sj; uiv = ij; lsv = sp; liv = ip; nlb = fminf(uy, ly);
    } else if (left) {
        usv = ssm; uiv = ism; lsv = sj; liv = ij; nlb = fminf(uy, ly);
    } else {
        nlb = -0.5f;
        float spu2 = 2.0f * ux, ipu = -ux * ux - 0.5f;
        float limit = spu2 * lx + ipu;
        float clm = (fabsf(lx) > ux) ? 1.0f : 0.0f;
        float clp = sigm_((clm - 0.5f) * 10.0f) * (ly - limit) + limit;
        if (clp < -0.5f) {
            float D = 4.0f * lx * lx - 4.0f * clp - 2.0f;
            float x2 = (2.0f * lx + sqrtf(fmaxf(D, 0.0f))) * 0.5f;
            lsv = 2.0f * x2; liv = -x2 * x2 - 0.5f;
        } else {
            lsv = (-0.5f - clp) / (0.0f - lx); liv = -0.5f;
        }
        float sl_ = sigm_(lx);
        float ssl = -sl_ * (1.0f - sl_), isl = -sl_ - ssl * lx;
        float stv = ssl * ux + isl - uy;
        if (stv > 0.0f) {
            float L = lx, R = 0.0f;
#pragma unroll
            for (int t = 0; t < 10; t++) {
                float m = 0.5f * (L + R);
                float s = sigm_(m);
                float sms = -s * (1.0f - s), ims = -s - sms * m;
                bool mask = (sms * ux + ims - uy) > 0.0f;
                L = mask ? m : L;
                R = mask ? R : m;
            }
            float scp = sigm_(-5.0f) * (L - lx) + lx;
            float sc = sigm_(scp);
            usv = -sc * (1.0f - sc);
            uiv = -sc - usv * scp;
        } else {
            usv = sj; uiv = ij;
        }
    }
    us[i] = usv; ui[i] = uiv; ls[i] = lsv; li[i] = liv;
    pub[i] = nub; plb[i] = nlb;
}

// Post-SPU back-substitution collapse (exact identity):
//   post_upper_r = sus_r * (sus_r>=0 ? Vu_r : Vl_r) + sui_r
//   post_lower_r = sls_r * (sls_r>=0 ? Vl_r : Vu_r) + sli_r
// where Vu/Vl are the RAW descended values of the pre-SPU chains of the same layer.
__global__ void k_postspu(const float* __restrict__ sus, const float* __restrict__ sui,
                          const float* __restrict__ sls, const float* __restrict__ sli,
                          const float* __restrict__ rawVu, const float* __restrict__ rawVl,
                          float* __restrict__ pub, float* __restrict__ plb) {
    int i = blockIdx.x * blockDim.x + threadIdx.x;
    if (i >= H) return;
    float su = sus[i], iu = sui[i];
    float vu = (su >= 0.0f) ? rawVu[i] : rawVl[i];
    pub[i] = fminf(pub[i], su * vu + iu);
    float sl = sls[i], il = sli[i];
    float vl = (sl >= 0.0f) ? rawVl[i] : rawVu[i];
    plb[i] = fmaxf(plb[i], sl * vl + il);
}

// Column-scale through a diagonal SPU layer, emitting bf16 hi/lo A operands.
__global__ void k_colscale(const float* __restrict__ Wsrc, const float* __restrict__ Bsrc,
                           int srcHalf,
                           const float* __restrict__ sus, const float* __restrict__ sui,
                           const float* __restrict__ sls, const float* __restrict__ sli,
                           const float* __restrict__ blayer,
                           __nv_bfloat16* __restrict__ Ahi, __nv_bfloat16* __restrict__ Alo,
                           float* __restrict__ Bdst, int Mu) {
    int row = blockIdx.x;
    bool up = row < Mu;
    int orow = up ? row : row - Mu;
    int srow = srcHalf ? orow : row;
    const float4* ws = (const float4*)(Wsrc + (long)srow * H);
    __nv_bfloat162* ah = (__nv_bfloat162*)(Ahi + (long)row * H);
    __nv_bfloat162* al = (__nv_bfloat162*)(Alo + (long)row * H);
    float bbase = Bsrc[srcHalf ? srow : row];
    const float4* ps = (const float4*)(up ? sus : sls);
    const float4* pi = (const float4*)(up ? sui : sli);
    const float4* ns = (const float4*)(up ? sls : sus);
    const float4* ni = (const float4*)(up ? sli : sui);
    const float4* bl = (const float4*)blayer;
    float acc = 0.0f;
    for (int j = threadIdx.x; j < H / 4; j += blockDim.x) {
        float4 w = ws[j];
        float4 psv = ps[j], piv = pi[j], nsv = ns[j], niv = ni[j], blv = bl[j];
        float4 o;
        float p, n;
        p = fmaxf(w.x, 0.0f); n = fminf(w.x, 0.0f); o.x = p * psv.x + n * nsv.x; acc += p * piv.x + n * niv.x + o.x * blv.x;
        p = fmaxf(w.y, 0.0f); n = fminf(w.y, 0.0f); o.y = p * psv.y + n * nsv.y; acc += p * piv.y + n * niv.y + o.y * blv.y;
        p = fmaxf(w.z, 0.0f); n = fminf(w.z, 0.0f); o.z = p * psv.z + n * nsv.z; acc += p * piv.z + n * niv.z + o.z * blv.z;
        p = fmaxf(w.w, 0.0f); n = fminf(w.w, 0.0f); o.w = p * psv.w + n * nsv.w; acc += p * piv.w + n * niv.w + o.w * blv.w;
        __nv_bfloat16 hx = __float2bfloat16(o.x), hy = __float2bfloat16(o.y);
        __nv_bfloat16 hz = __float2bfloat16(o.z), hw = __float2bfloat16(o.w);
        __nv_bfloat16 lx = __float2bfloat16(o.x - __bfloat162float(hx));
        __nv_bfloat16 ly = __float2bfloat16(o.y - __bfloat162float(hy));
        __nv_bfloat16 lz = __float2bfloat16(o.z - __bfloat162float(hz));
        __nv_bfloat16 lw = __float2bfloat16(o.w - __bfloat162float(hw));
        ah[2 * j]     = __halves2bfloat162(hx, hy);
        ah[2 * j + 1] = __halves2bfloat162(hz, hw);
        al[2 * j]     = __halves2bfloat162(lx, ly);
        al[2 * j + 1] = __halves2bfloat162(lz, lw);
    }
    float r = block_reduce(acc);
    if (threadIdx.x == 0) Bdst[row] = bbase + r;
}

// Final interval evaluation at the input layer; writes raw value (optional) and refines bounds.
__global__ void k_interval_f(const float* __restrict__ W, int ld,
                             const float* __restrict__ bvec,
                             const float* __restrict__ u0, const float* __restrict__ l0,
                             float* __restrict__ ubio, float* __restrict__ lbio,
                             float* __restrict__ rawV,
                             int cols, int Mu) {
    int row = blockIdx.x;
    bool up = row < Mu;
    int orow = up ? row : row - Mu;
    const float4* wr = (const float4*)(W + (long)row * ld);
    const float4* a4 = (const float4*)(up ? u0 : l0);
    const float4* c4p = (const float4*)(up ? l0 : u0);
    float acc = 0.0f;
    for (int j = threadIdx.x; j < cols / 4; j += blockDim.x) {
        float4 w = wr[j];
        float4 av = a4[j], cv = c4p[j];
        acc += fmaxf(w.x, 0.0f) * av.x + fminf(w.x, 0.0f) * cv.x;
        acc += fmaxf(w.y, 0.0f) * av.y + fminf(w.y, 0.0f) * cv.y;
        acc += fmaxf(w.z, 0.0f) * av.z + fminf(w.z, 0.0f) * cv.z;
        acc += fmaxf(w.w, 0.0f) * av.w + fminf(w.w, 0.0f) * cv.w;
    }
    float r = block_reduce(acc);
    if (threadIdx.x == 0) {
        float v = r + bvec[row];
        if (rawV) rawV[row] = v;
        if (up) ubio[orow] = fminf(ubio[orow], v);
        else    lbio[orow] = fmaxf(lbio[orow], v);
    }
}

// ---------------- bf16-split GEMM via mma.sync (HMMA) ----------------
#define GSTRIDE 80
#define TILEB   (128 * GSTRIDE)
#define STAGEB  (4 * TILEB)
#define GEMM_SMEM (2 * STAGEB)

__global__ __launch_bounds__(256) void gemm_mma(
    const __nv_bfloat16* __restrict__ Ahi, const __nv_bfloat16* __restrict__ Alo,
    const __nv_bfloat16* __restrict__ Bhi, const __nv_bfloat16* __restrict__ Blo,
    float* __restrict__ C, int M, int ldc) {
    extern __shared__ char dynsm[];
    const int tid = threadIdx.x;
    const int wid = tid >> 5;
    const int lane = tid & 31;
    const int rowBase = blockIdx.y * 128;
    const int colBase = blockIdx.x * 128;
    const uint32_t smbase = smem_u32(dynsm);

    const int wm = wid & 1, wn = wid >> 1;
    const int mbase = wm * 64, nbase = wn * 32;
    const int lr = lane >> 2, lc2 = 2 * (lane & 3);

    float acc[4][4][4];
#pragma unroll
    for (int mi = 0; mi < 4; mi++)
#pragma unroll
        for (int ni = 0; ni < 4; ni++)
#pragma unroll
            for (int t = 0; t < 4; t++) acc[mi][ni][t] = 0.0f;

    auto issue = [&](int c) {
        const int st = c & 1;
        const uint32_t base = smbase + st * STAGEB;
        const long k0 = (long)c * 32;
#pragma unroll
        for (int p = 0; p < 2; p++) {
            int u = tid + p * 256;
            int row = u >> 2, seg = u & 3;
            uint32_t so = base + row * GSTRIDE + seg * 16;
            long ka = k0 + seg * 8;
            int grow = rowBase + row; if (grow > M - 1) grow = M - 1;
            cp16(so,              Ahi + (long)grow * H + ka);
            cp16(so + TILEB,      Alo + (long)grow * H + ka);
            int gn = colBase + row;
            cp16(so + 2 * TILEB,  Bhi + (long)gn * H + ka);
            cp16(so + 3 * TILEB,  Blo + (long)gn * H + ka);
        }
        asm volatile("cp.async.commit_group;");
    };

    issue(0);
    const int NK = H / 32;
    for (int c = 0; c < NK; ++c) {
        if (c + 1 < NK) {
            issue(c + 1);
            asm volatile("cp.async.wait_group 1;");
        } else {
            asm volatile("cp.async.wait_group 0;");
        }
        __syncthreads();
        const char* sb = dynsm + (c & 1) * STAGEB;
        const char* sA = sb;
        const char* sB = sb + 2 * TILEB;
#pragma unroll
        for (int kk = 0; kk < 32; kk += 16) {
            uint32_t bh[4][2], blo[4][2];
#pragma unroll
            for (int ni = 0; ni < 4; ni++) {
                const char* p = sB + (nbase + ni * 8 + lr) * GSTRIDE + (kk + lc2) * 2;
                bh[ni][0]  = *(const uint32_t*)p;
                bh[ni][1]  = *(const uint32_t*)(p + 16);
                blo[ni][0] = *(const uint32_t*)(p + TILEB);
                blo[ni][1] = *(const uint32_t*)(p + TILEB + 16);
            }
#pragma unroll
            for (int mi = 0; mi < 4; mi++) {
                const char* q = sA + (mbase + mi * 16 + lr) * GSTRIDE + (kk + lc2) * 2;
                uint32_t ah[4], al[4];
                ah[0] = *(const uint32_t*)q;
                ah[1] = *(const uint32_t*)(q + 8 * GSTRIDE);
                ah[2] = *(const uint32_t*)(q + 16);
                ah[3] = *(const uint32_t*)(q + 8 * GSTRIDE + 16);
                al[0] = *(const uint32_t*)(q + TILEB);
                al[1] = *(const uint32_t*)(q + TILEB + 8 * GSTRIDE);
                al[2] = *(const uint32_t*)(q + TILEB + 16);
                al[3] = *(const uint32_t*)(q + TILEB + 8 * GSTRIDE + 16);
#pragma unroll
                for (int ni = 0; ni < 4; ni++) {
                    mma16816(acc[mi][ni], ah, bh[ni]);
                    mma16816(acc[mi][ni], ah, blo[ni]);
                    mma16816(acc[mi][ni], al, bh[ni]);
                }
            }
        }
        __syncthreads();
    }

#pragma unroll
    for (int mi = 0; mi < 4; mi++) {
        int gr0 = rowBase + mbase + mi * 16 + lr;
#pragma unroll
        for (int ni = 0; ni < 4; ni++) {
            int gc = colBase + nbase + ni * 8 + lc2;
            if (gr0 < M) {
                float2 v = make_float2(acc[mi][ni][0], acc[mi][ni][1]);
                *(float2*)(C + (long)gr0 * ldc + gc) = v;
            }
            if (gr0 + 8 < M) {
                float2 v = make_float2(acc[mi][ni][2], acc[mi][ni][3]);
                *(float2*)(C + (long)(gr0 + 8) * ldc + gc) = v;
            }
        }
    }
}

__global__ void k_final_min(const float* __restrict__ lb4, float* __restrict__ out) {
    if (threadIdx.x == 0) {
        float m = lb4[0];
#pragma unroll
        for (int i = 1; i < DOUT; i++) m = fminf(m, lb4[i]);
        out[0] = m;
    }
}

// ---------------- host orchestration ----------------
extern "C" void kernel_launch(void* const* d_in, const int* in_sizes, int n_in,
                              void* d_out, int out_size) {
    (void)in_sizes; (void)n_in; (void)out_size;
    const float* inputs = (const float*)d_in[0];
    const float* eps    = (const float*)d_in[1];
    const float* w1 = (const float*)d_in[2]; const float* b1 = (const float*)d_in[3];
    const float* w2 = (const float*)d_in[4]; const float* b2 = (const float*)d_in[5];
    const float* w3 = (const float*)d_in[6]; const float* b3 = (const float*)d_in[7];
    const float* w4 = (const float*)d_in[8]; const float* b4 = (const float*)d_in[9];
    float* out = (float*)d_out;

    cudaFuncSetAttribute(gemm_mma, cudaFuncAttributeMaxDynamicSharedMemorySize, GEMM_SMEM);

    float *U0, *L0, *UBL, *LBL, *SUS, *SUI, *SLS, *SLI, *PUB, *PLB, *UB4, *LB4, *RAWV;
    float *W0, *W1b, *B0, *B1;
    __nv_bfloat16 *AHI, *ALO, *T1H, *T1L, *T2H, *T2L, *T3H, *T3L;
    cudaGetSymbolAddress((void**)&U0, g_u0);
    cudaGetSymbolAddress((void**)&L0, g_l0);
    cudaGetSymbolAddress((void**)&UBL, g_ubL);
    cudaGetSymbolAddress((void**)&LBL, g_lbL);
    cudaGetSymbolAddress((void**)&SUS, g_sus);
    cudaGetSymbolAddress((void**)&SUI, g_sui);
    cudaGetSymbolAddress((void**)&SLS, g_sls);
    cudaGetSymbolAddress((void**)&SLI, g_sli);
    cudaGetSymbolAddress((void**)&PUB, g_pub);
    cudaGetSymbolAddress((void**)&PLB, g_plb);
    cudaGetSymbolAddress((void**)&UB4, g_ub4);
    cudaGetSymbolAddress((void**)&LB4, g_lb4);
    cudaGetSymbolAddress((void**)&RAWV, g_rawV);
    cudaGetSymbolAddress((void**)&W0, g_W0);
    cudaGetSymbolAddress((void**)&W1b, g_W1);
    cudaGetSymbolAddress((void**)&B0, g_B0);
    cudaGetSymbolAddress((void**)&B1, g_B1);
    cudaGetSymbolAddress((void**)&AHI, g_Ahi);
    cudaGetSymbolAddress((void**)&ALO, g_Alo);
    cudaGetSymbolAddress((void**)&T1H, g_T1hi);
    cudaGetSymbolAddress((void**)&T1L, g_T1lo);
    cudaGetSymbolAddress((void**)&T2H, g_T2hi);
    cudaGetSymbolAddress((void**)&T2L, g_T2lo);
    cudaGetSymbolAddress((void**)&T3H, g_T3hi);
    cudaGetSymbolAddress((void**)&T3L, g_T3lo);

    const float* LBv[3] = {b1, b2, b3};
    const __nv_bfloat16* TH[3] = {T1H, T2H, T3H};
    const __nv_bfloat16* TL[3] = {T1L, T2L, T3L};

    // transposed + split weights (B operands)
    k_transpose_split<<<dim3(NPAD1 / 32, H / 32), dim3(32, 8)>>>(w1, T1H, T1L, DIN);
    k_transpose_split<<<dim3(H / 32, H / 32),     dim3(32, 8)>>>(w2, T2H, T2L, H);
    k_transpose_split<<<dim3(H / 32, H / 32),     dim3(32, 8)>>>(w3, T3H, T3L, H);

    // Pre-SPU (first back-substitution) descend of W_l down to the input box.
    auto descend = [&](const float* sW, const float* sB, int M, int Mu, int lvl,
                       float* ubio, float* lbio, float* rawV) {
        const float* curW = sW;
        const float* curB = sB;
        int curHalf = 1;
        float* bw[2] = {W0, W1b};
        float* bb[2] = {B0, B1};
        int pw = 0, pb = 0;
        int curLd = H;
        for (int l = lvl; l >= 1; --l) {
            float* tB = bb[pb];
            k_colscale<<<M, 256>>>(curW, curB, curHalf,
                                   SUS + (l - 1) * H, SUI + (l - 1) * H,
                                   SLS + (l - 1) * H, SLI + (l - 1) * H,
                                   LBv[l - 1], AHI, ALO, tB, Mu);
            int Npad = (l == 1) ? NPAD1 : H;
            float* oW = bw[pw];
            dim3 g(Npad / 128, (M + 127) / 128);
            gemm_mma<<<g, 256, GEMM_SMEM>>>(AHI, ALO, TH[l - 1], TL[l - 1], oW, M, Npad);
            curW = oW; curB = tB;
            curHalf = 0;
            pw ^= 1; pb ^= 1;
            curLd = Npad;
        }
        k_interval_f<<<M, 256>>>(curW, curLd, curB, U0, L0, ubio, lbio, rawV, DIN, Mu);
    };

    // input box (normalized)
    k_init_bounds<<<(DIN + 255) / 256, 256>>>(inputs, eps, U0, L0);

    // ---- layer 1 ----
    k_affine_interval<<<H, 256>>>(w1, b1, U0, L0, UBL + 0 * H, LBL + 0 * H, DIN);
    k_spu<<<(H + 255) / 256, 256>>>(UBL + 0 * H, LBL + 0 * H,
                                    SUS + 0 * H, SUI + 0 * H, SLS + 0 * H, SLI + 0 * H,
                                    PUB + 0 * H, PLB + 0 * H);
    // post-SPU refinement collapses to the identity (raw V = layer-1 interval values)
    k_postspu<<<(H + 255) / 256, 256>>>(SUS + 0 * H, SUI + 0 * H, SLS + 0 * H, SLI + 0 * H,
                                        UBL + 0 * H, LBL + 0 * H, PUB + 0 * H, PLB + 0 * H);

    // ---- layer 2 ----
    k_affine_interval<<<H, 256>>>(w2, b2, PUB + 0 * H, PLB + 0 * H,
                                  UBL + 1 * H, LBL + 1 * H, H);
    descend(w2, b2, 2 * H, H, 1, UBL + 1 * H, LBL + 1 * H, RAWV);
    k_spu<<<(H + 255) / 256, 256>>>(UBL + 1 * H, LBL + 1 * H,
                                    SUS + 1 * H, SUI + 1 * H, SLS + 1 * H, SLI + 1 * H,
                                    PUB + 1 * H, PLB + 1 * H);
    k_postspu<<<(H + 255) / 256, 256>>>(SUS + 1 * H, SUI + 1 * H, SLS + 1 * H, SLI + 1 * H,
                                        RAWV, RAWV + H, PUB + 1 * H, PLB + 1 * H);

    // ---- layer 3 ----
    k_affine_interval<<<H, 256>>>(w3, b3, PUB + 1 * H, PLB + 1 * H,
                                  UBL + 2 * H, LBL + 2 * H, H);
    descend(w3, b3, 2 * H, H, 2, UBL + 2 * H, LBL + 2 * H, RAWV);
    k_spu<<<(H + 255) / 256, 256>>>(UBL + 2 * H, LBL + 2 * H,
                                    SUS + 2 * H, SUI + 2 * H, SLS + 2 * H, SLI + 2 * H,
                                    PUB + 2 * H, PLB + 2 * H);
    k_postspu<<<(H + 255) / 256, 256>>>(SUS + 2 * H, SUI + 2 * H, SLS + 2 * H, SLI + 2 * H,
                                        RAWV, RAWV + H, PUB + 2 * H, PLB + 2 * H);

    // ---- layer 4 (only the lower bound matters for the output) ----
    k_affine_interval<<<DOUT, 256>>>(w4, b4, PUB + 2 * H, PLB + 2 * H, UB4, LB4, H);
    descend(w4, b4, DOUT, 0, 3, nullptr, LB4, nullptr);

    k_final_min<<<1, 32>>>(LB4, out);
}